// round 1
// baseline (speedup 1.0000x reference)
#include <cuda_runtime.h>
#include <math.h>
#include <stdint.h>
#include <stddef.h>

// ---------------- problem constants ----------------
#define NSC 48
#define NVC 10
#define IN_SIZE 156          // 48 + 30 + 30 + 48
#define HID 96               // hidden / edge-feature width (both 96)
#define WN 6928              // total per-edge weight numel
#define MAX_E 50000
#define MAX_N 10000

// w segment offsets
#define OFF_0E 0             // 58 x 48
#define OFF_1O 2784          // 68 x 10
#define OFF_1E 3464          // 68 x 10
#define OFF_0O 4144          // 58 x 48

// ---------------- scratch (device globals; no allocation) ----------------
__device__ float g_h[(size_t)MAX_E * HID];
__device__ float g_w[(size_t)MAX_E * WN];
__device__ float g_seg[(size_t)MAX_N * IN_SIZE];
__device__ float g_cnt[MAX_N];

// ---------------- zero-init ----------------
__global__ void zero_k(int nn) {
    int i = blockIdx.x * blockDim.x + threadIdx.x;
    int ns = nn * IN_SIZE;
    if (i < ns) g_seg[i] = 0.0f;
    if (i < nn) g_cnt[i] = 0.0f;
}

// ---------------- tiled fp32 GEMM:  C[M][NTOT] = op(A[M][96] @ B[96][NTOT] + bias) ----------------
// MT=128 rows, NT=64 cols per CTA, 256 threads, 8x4 register tile, K split in 2x48.
template<int NTOT, bool RELU, bool A_IS_GH, bool C_IS_GH>
__global__ __launch_bounds__(256) void gemm_k(const float* __restrict__ A,
                                              const float* __restrict__ B,
                                              const float* __restrict__ bias,
                                              int M) {
    __shared__ float sA[48 * 132];   // transposed: sA[k][e], row stride 132 (conflict-free-ish, 16B aligned)
    __shared__ float sB[48 * 64];    // sB[k][j]

    const float* Ap = A_IS_GH ? (const float*)g_h : A;
    float* C        = C_IS_GH ? (float*)g_h : (float*)g_w;

    const int n0 = blockIdx.x * 64;
    const int m0 = blockIdx.y * 128;
    const int tid = threadIdx.x;
    const int tmi = tid >> 4;    // 0..15
    const int tni = tid & 15;    // 0..15

    float acc[8][4];
#pragma unroll
    for (int mm = 0; mm < 8; mm++)
#pragma unroll
        for (int nn = 0; nn < 4; nn++) acc[mm][nn] = 0.0f;

#pragma unroll
    for (int p = 0; p < 2; p++) {
        const int kb = p * 48;
        // load A tile (128 rows x 48 k) transposed into sA
#pragma unroll
        for (int it = 0; it < 6; it++) {
            int idx = tid + it * 256;            // 0..1535
            int e  = idx / 12;
            int k4 = idx % 12;
            float4 v = make_float4(0.f, 0.f, 0.f, 0.f);
            if (m0 + e < M)
                v = *(const float4*)(Ap + (size_t)(m0 + e) * HID + kb + k4 * 4);
            sA[(k4 * 4 + 0) * 132 + e] = v.x;
            sA[(k4 * 4 + 1) * 132 + e] = v.y;
            sA[(k4 * 4 + 2) * 132 + e] = v.z;
            sA[(k4 * 4 + 3) * 132 + e] = v.w;
        }
        // load B tile (48 k x 64 j)
#pragma unroll
        for (int it = 0; it < 3; it++) {
            int idx = tid + it * 256;            // 0..767
            int k  = idx / 16;
            int j4 = idx % 16;
            int j  = n0 + j4 * 4;
            float4 v = make_float4(0.f, 0.f, 0.f, 0.f);
            if (j < NTOT)
                v = *(const float4*)(B + (size_t)(kb + k) * NTOT + j);
            *(float4*)(sB + k * 64 + j4 * 4) = v;
        }
        __syncthreads();

#pragma unroll 8
        for (int k = 0; k < 48; k++) {
            float4 a0 = *(float4*)(sA + k * 132 + tmi * 8);
            float4 a1 = *(float4*)(sA + k * 132 + tmi * 8 + 4);
            float4 b  = *(float4*)(sB + k * 64 + tni * 4);
            float av[8] = {a0.x, a0.y, a0.z, a0.w, a1.x, a1.y, a1.z, a1.w};
            float bv[4] = {b.x, b.y, b.z, b.w};
#pragma unroll
            for (int mm = 0; mm < 8; mm++)
#pragma unroll
                for (int nn = 0; nn < 4; nn++)
                    acc[mm][nn] += av[mm] * bv[nn];
        }
        __syncthreads();
    }

    // epilogue: bias (+relu) and store
    const int n = n0 + tni * 4;
    float bb[4];
#pragma unroll
    for (int nn = 0; nn < 4; nn++) bb[nn] = (n + nn < NTOT) ? bias[n + nn] : 0.0f;

#pragma unroll
    for (int mm = 0; mm < 8; mm++) {
        int e = m0 + tmi * 8 + mm;
        if (e >= M) continue;
        float v0 = acc[mm][0] + bb[0];
        float v1 = acc[mm][1] + bb[1];
        float v2 = acc[mm][2] + bb[2];
        float v3 = acc[mm][3] + bb[3];
        if (RELU) {
            v0 = fmaxf(v0, 0.f); v1 = fmaxf(v1, 0.f);
            v2 = fmaxf(v2, 0.f); v3 = fmaxf(v3, 0.f);
        }
        if (n + 3 < NTOT) {
            float4 v = make_float4(v0, v1, v2, v3);
            *(float4*)(C + (size_t)e * NTOT + n) = v;
        } else {
            if (n + 0 < NTOT) C[(size_t)e * NTOT + n + 0] = v0;
            if (n + 1 < NTOT) C[(size_t)e * NTOT + n + 1] = v1;
            if (n + 2 < NTOT) C[(size_t)e * NTOT + n + 2] = v2;
            if (n + 3 < NTOT) C[(size_t)e * NTOT + n + 3] = v3;
        }
    }
}

// ---------------- per-edge tensor-product epilogue ----------------
// One CTA (192 threads) per edge. Computes the 524 TP coefficients in smem,
// then thread t (<156) contracts coefficient vector with the w row and
// atomically accumulates into g_seg[src].
__global__ __launch_bounds__(192) void tp_epilogue(const float* __restrict__ node_attr,
                                                   const int*  __restrict__ edge_index,
                                                   const float* __restrict__ edge_sh,
                                                   int E) {
    const int e = blockIdx.x;
    if (e >= E) return;
    __shared__ float sx[IN_SIZE];
    __shared__ float sc0e[58];
    __shared__ float sc1o[204];   // [i*3 + c]
    __shared__ float sc1e[204];
    __shared__ float sc0o[58];
    __shared__ float ssh[4];
    __shared__ int s_src;

    const int t = threadIdx.x;
    if (t == 0) s_src = edge_index[e];
    if (t < 4)  ssh[t] = edge_sh[(size_t)e * 4 + t];
    {
        const int dst = edge_index[E + e];
        const float* xr = node_attr + (size_t)dst * IN_SIZE;
        for (int i = t; i < IN_SIZE; i += 192) sx[i] = xr[i];
    }
    __syncthreads();

    const float sh0 = ssh[0], s1x = ssh[1], s1y = ssh[2], s1z = ssh[3];
    const float inv_s3 = 0.57735026918962576f;
    const float inv_s2 = 0.70710678118654752f;

    if (t < 58) {
        // out_0e
        if (t < 48) sc0e[t] = sx[t] * sh0;
        else {
            int b = 48 + (t - 48) * 3;
            sc0e[t] = inv_s3 * (sx[b] * s1x + sx[b + 1] * s1y + sx[b + 2] * s1z);
        }
        // out_0o
        if (t < 10) {
            int b = 78 + t * 3;
            sc0o[t] = inv_s3 * (sx[b] * s1x + sx[b + 1] * s1y + sx[b + 2] * s1z);
        } else {
            sc0o[t] = sx[108 + t - 10] * sh0;
        }
    }
    if (t < 68) {
        float v0, v1, v2;
        // out_1o
        if (t < 48) {
            float xv = sx[t];
            v0 = xv * s1x; v1 = xv * s1y; v2 = xv * s1z;
        } else if (t < 58) {
            int b = 48 + (t - 48) * 3;
            v0 = sx[b] * sh0; v1 = sx[b + 1] * sh0; v2 = sx[b + 2] * sh0;
        } else {
            int b = 78 + (t - 58) * 3;       // cross(in_1e, sh1) * inv_s2
            float a0 = sx[b], a1 = sx[b + 1], a2 = sx[b + 2];
            v0 = (a1 * s1z - a2 * s1y) * inv_s2;
            v1 = (a2 * s1x - a0 * s1z) * inv_s2;
            v2 = (a0 * s1y - a1 * s1x) * inv_s2;
        }
        sc1o[t * 3 + 0] = v0; sc1o[t * 3 + 1] = v1; sc1o[t * 3 + 2] = v2;
        // out_1e
        if (t < 10) {
            int b = 48 + t * 3;              // cross(in_1o, sh1) * inv_s2
            float a0 = sx[b], a1 = sx[b + 1], a2 = sx[b + 2];
            v0 = (a1 * s1z - a2 * s1y) * inv_s2;
            v1 = (a2 * s1x - a0 * s1z) * inv_s2;
            v2 = (a0 * s1y - a1 * s1x) * inv_s2;
        } else if (t < 20) {
            int b = 78 + (t - 10) * 3;
            v0 = sx[b] * sh0; v1 = sx[b + 1] * sh0; v2 = sx[b + 2] * sh0;
        } else {
            float xv = sx[108 + (t - 20)];
            v0 = xv * s1x; v1 = xv * s1y; v2 = xv * s1z;
        }
        sc1e[t * 3 + 0] = v0; sc1e[t * 3 + 1] = v1; sc1e[t * 3 + 2] = v2;
    }
    __syncthreads();

    const float* wr = g_w + (size_t)e * WN;
    const float rs58 = 0.13130643285972254f;   // 1/sqrt(58)
    const float rs68 = 0.12126781251816648f;   // 1/sqrt(68)

    if (t < IN_SIZE) {
        float y = 0.0f;
        if (t < 48) {
#pragma unroll
            for (int i = 0; i < 58; i++) y += sc0e[i] * __ldg(wr + OFF_0E + i * 48 + t);
            y *= rs58;
        } else if (t < 108) {
            const float* sc;
            int u, base;
            if (t < 78) { u = t - 48; base = OFF_1O; sc = sc1o; }
            else        { u = t - 78; base = OFF_1E; sc = sc1e; }
            int ov = u / 3;
            int c  = u - ov * 3;
#pragma unroll
            for (int i = 0; i < 68; i++) y += sc[i * 3 + c] * __ldg(wr + base + i * 10 + ov);
            y *= rs68;
        } else {
            int oo = t - 108;
#pragma unroll
            for (int i = 0; i < 58; i++) y += sc0o[i] * __ldg(wr + OFF_0O + i * 48 + oo);
            y *= rs58;
        }
        atomicAdd(g_seg + (size_t)s_src * IN_SIZE + t, y);
    }
    if (t == IN_SIZE) atomicAdd(g_cnt + s_src, 1.0f);
}

// ---------------- finalize: out = seg / max(cnt,1) + node_attr ----------------
__global__ void finalize_k(const float* __restrict__ node_attr,
                           float* __restrict__ out, int nn) {
    int i = blockIdx.x * blockDim.x + threadIdx.x;
    if (i < nn * IN_SIZE) {
        float c = g_cnt[i / IN_SIZE];
        out[i] = g_seg[i] / fmaxf(c, 1.0f) + node_attr[i];
    }
}

// ---------------- launch ----------------
extern "C" void kernel_launch(void* const* d_in, const int* in_sizes, int n_in,
                              void* d_out, int out_size) {
    const float* node_attr  = (const float*)d_in[0];
    const int*   edge_index = (const int*)d_in[1];
    const float* edge_attr  = (const float*)d_in[2];
    const float* edge_sh    = (const float*)d_in[3];
    const float* W1         = (const float*)d_in[4];
    const float* b1         = (const float*)d_in[5];
    const float* W2         = (const float*)d_in[6];
    const float* b2         = (const float*)d_in[7];
    float* out = (float*)d_out;

    const int E  = in_sizes[2] / HID;       // edge_attr numel / 96
    const int Nn = in_sizes[0] / IN_SIZE;   // node_attr numel / 156

    // zero accumulators
    zero_k<<<(Nn * IN_SIZE + 255) / 256, 256>>>(Nn);

    // h = relu(edge_attr @ W1 + b1)   (writes g_h)
    {
        dim3 grid((HID + 63) / 64, (E + 127) / 128);
        gemm_k<HID, true, false, true><<<grid, 256>>>(edge_attr, W1, b1, E);
    }
    // w = h @ W2 + b2                 (reads g_h, writes g_w)
    {
        dim3 grid((WN + 63) / 64, (E + 127) / 128);
        gemm_k<WN, false, true, false><<<grid, 256>>>(nullptr, W2, b2, E);
    }
    // per-edge tensor product + scatter
    tp_epilogue<<<E, 192>>>(node_attr, edge_index, edge_sh, E);

    // mean + residual
    finalize_k<<<(Nn * IN_SIZE + 255) / 256, 256>>>(node_attr, out, Nn);
}

// round 3
// speedup vs baseline: 1.2427x; 1.2427x over previous
#include <cuda_runtime.h>
#include <cuda_bf16.h>
#include <math.h>
#include <stdint.h>
#include <stddef.h>

// ---------------- problem constants ----------------
#define IN_SIZE 156          // 48 + 30 + 30 + 48
#define HID 96
#define WN 6928
#define MAX_E 50000
#define MAX_N 10000
#define KPAD 320             // row stride of split-bf16 operands; 288 used
#define KUSE 288             // 96(hi) + 96(hi) + 96(lo)

// w segment offsets
#define OFF_0E 0
#define OFF_1O 2784
#define OFF_1E 3464
#define OFF_0O 4144

// ---------------- scratch (device globals) ----------------
__device__ __nv_bfloat16 g_ha[(size_t)(MAX_E + 128) * KPAD];  // A' split bf16
__device__ __nv_bfloat16 g_bt[(size_t)(WN + 128) * KPAD];     // B'^T split bf16 [n][k]
__device__ float g_w[(size_t)MAX_E * WN];
__device__ float g_seg[(size_t)MAX_N * IN_SIZE];
__device__ float g_cnt[MAX_N];

// ---------------- PTX helpers (compute_103-safe only) ----------------
__device__ __forceinline__ uint32_t smem_u32(const void* p) {
    uint32_t a;
    asm("{ .reg .u64 t; cvta.to.shared.u64 t, %1; cvt.u32.u64 %0, t; }" : "=r"(a) : "l"(p));
    return a;
}
__device__ __forceinline__ void cp16(uint32_t d, const void* s, bool v) {
    int sz = v ? 16 : 0;
    asm volatile("cp.async.cg.shared.global [%0], [%1], 16, %2;" :: "r"(d), "l"(s), "r"(sz) : "memory");
}
__device__ __forceinline__ void cp_commit() { asm volatile("cp.async.commit_group;" ::: "memory"); }
template<int N> __device__ __forceinline__ void cp_wait() { asm volatile("cp.async.wait_group %0;" :: "n"(N) : "memory"); }

__device__ __forceinline__ void ldm_x4(uint32_t* r, uint32_t addr) {
    asm volatile("ldmatrix.sync.aligned.m8n8.x4.shared.b16 {%0,%1,%2,%3}, [%4];"
                 : "=r"(r[0]), "=r"(r[1]), "=r"(r[2]), "=r"(r[3]) : "r"(addr));
}
__device__ __forceinline__ void mma16816(float* d, const uint32_t* a, uint32_t b0, uint32_t b1) {
    asm volatile("mma.sync.aligned.m16n8k16.row.col.f32.bf16.bf16.f32 "
                 "{%0,%1,%2,%3}, {%4,%5,%6,%7}, {%8,%9}, {%0,%1,%2,%3};"
                 : "+f"(d[0]), "+f"(d[1]), "+f"(d[2]), "+f"(d[3])
                 : "r"(a[0]), "r"(a[1]), "r"(a[2]), "r"(a[3]), "r"(b0), "r"(b1));
}

// ---------------- zero-init ----------------
__global__ void zero_k(int nn) {
    int i = blockIdx.x * blockDim.x + threadIdx.x;
    int ns = nn * IN_SIZE;
    if (i < ns) g_seg[i] = 0.0f;
    if (i < nn) g_cnt[i] = 0.0f;
}

// ---------------- h GEMM (fp32 SIMT): g_ha = split_bf16(relu(edge_attr@W1 + b1)) ----------------
__global__ __launch_bounds__(256) void hgemm_k(const float* __restrict__ A,
                                               const float* __restrict__ B,
                                               const float* __restrict__ bias,
                                               int M) {
    __shared__ float sA[48 * 132];
    __shared__ float sB[48 * 64];

    const int n0 = blockIdx.x * 64;
    const int m0 = blockIdx.y * 128;
    const int tid = threadIdx.x;
    const int tmi = tid >> 4;
    const int tni = tid & 15;

    float acc[8][4];
#pragma unroll
    for (int mm = 0; mm < 8; mm++)
#pragma unroll
        for (int nn = 0; nn < 4; nn++) acc[mm][nn] = 0.0f;

#pragma unroll
    for (int p = 0; p < 2; p++) {
        const int kb = p * 48;
#pragma unroll
        for (int it = 0; it < 6; it++) {
            int idx = tid + it * 256;
            int e = idx / 12;
            int k4 = idx % 12;
            float4 v = make_float4(0.f, 0.f, 0.f, 0.f);
            if (m0 + e < M)
                v = *(const float4*)(A + (size_t)(m0 + e) * HID + kb + k4 * 4);
            sA[(k4 * 4 + 0) * 132 + e] = v.x;
            sA[(k4 * 4 + 1) * 132 + e] = v.y;
            sA[(k4 * 4 + 2) * 132 + e] = v.z;
            sA[(k4 * 4 + 3) * 132 + e] = v.w;
        }
#pragma unroll
        for (int it = 0; it < 3; it++) {
            int idx = tid + it * 256;
            int k = idx / 16;
            int j4 = idx % 16;
            int j = n0 + j4 * 4;
            float4 v = make_float4(0.f, 0.f, 0.f, 0.f);
            if (j < HID)
                v = *(const float4*)(B + (size_t)(kb + k) * HID + j);
            *(float4*)(sB + k * 64 + j4 * 4) = v;
        }
        __syncthreads();

#pragma unroll 8
        for (int k = 0; k < 48; k++) {
            float4 a0 = *(float4*)(sA + k * 132 + tmi * 8);
            float4 a1 = *(float4*)(sA + k * 132 + tmi * 8 + 4);
            float4 b = *(float4*)(sB + k * 64 + tni * 4);
            float av[8] = {a0.x, a0.y, a0.z, a0.w, a1.x, a1.y, a1.z, a1.w};
            float bv[4] = {b.x, b.y, b.z, b.w};
#pragma unroll
            for (int mm = 0; mm < 8; mm++)
#pragma unroll
                for (int nn = 0; nn < 4; nn++)
                    acc[mm][nn] += av[mm] * bv[nn];
        }
        __syncthreads();
    }

    const int n = n0 + tni * 4;
#pragma unroll
    for (int mm = 0; mm < 8; mm++) {
        int e = m0 + tmi * 8 + mm;
        if (e >= M) continue;
        size_t rb = (size_t)e * KPAD;
#pragma unroll
        for (int nn = 0; nn < 4; nn++) {
            int nc = n + nn;
            if (nc >= HID) continue;
            float v = fmaxf(acc[mm][nn] + bias[nc], 0.0f);
            __nv_bfloat16 hi = __float2bfloat16(v);
            __nv_bfloat16 lo = __float2bfloat16(v - __bfloat162float(hi));
            g_ha[rb + nc] = hi;
            g_ha[rb + 96 + nc] = hi;
            g_ha[rb + 192 + nc] = lo;
        }
    }
}

// ---------------- B' conversion: W2[96][6928] fp32 -> g_bt[6928][320] bf16 ----------------
__global__ void convB_k(const float* __restrict__ W2) {
    int i = blockIdx.x * blockDim.x + threadIdx.x;
    if (i >= HID * WN) return;
    int k = i / WN;
    int n = i - k * WN;
    float v = W2[i];
    __nv_bfloat16 hi = __float2bfloat16(v);
    __nv_bfloat16 lo = __float2bfloat16(v - __bfloat162float(hi));
    size_t rb = (size_t)n * KPAD;
    g_bt[rb + k] = hi;          // pairs with Ah
    g_bt[rb + 96 + k] = lo;     // pairs with Ah
    g_bt[rb + 192 + k] = hi;    // pairs with Al
}

// ---------------- w GEMM via mma.sync (HMMA bf16) ----------------
// 128x128 tile per CTA, 256 threads = 8 warps (4M x 2N), each warp 32x64.
// K = 288 in 9 blocks of 32, double-buffered cp.async, padded smem (stride 40).
#define SAS 40
__global__ __launch_bounds__(256) void wgemm_mma(const float* __restrict__ b2, int E) {
    __shared__ __nv_bfloat16 sA[2][128 * SAS];
    __shared__ __nv_bfloat16 sB[2][128 * SAS];

    const int tid = threadIdx.x;
    const int wid = tid >> 5;
    const int lid = tid & 31;
    const int wm = wid >> 1;     // 0..3 -> rows wm*32
    const int wn = wid & 1;      // 0..1 -> cols wn*64
    const int n0 = blockIdx.x * 128;
    const int m0 = blockIdx.y * 128;

    const uint32_t aS[2] = { smem_u32(sA[0]), smem_u32(sA[1]) };
    const uint32_t bS[2] = { smem_u32(sB[0]), smem_u32(sB[1]) };

    float acc[2][8][4];
#pragma unroll
    for (int mt = 0; mt < 2; mt++)
#pragma unroll
        for (int nt = 0; nt < 8; nt++)
#pragma unroll
            for (int q = 0; q < 4; q++) acc[mt][nt][q] = 0.0f;

    // loader: K-block kb into buffer buf (A: rows m0.., B: rows n0..; 64B/row = 4x16B)
    auto load_blk = [&](int kb, int buf) {
#pragma unroll
        for (int i = 0; i < 2; i++) {
            int idx = tid + i * 256;         // 0..511
            int row = idx >> 2;
            int ch  = idx & 3;
            {
                bool v = (m0 + row) < E;
                int r = v ? (m0 + row) : 0;
                cp16(aS[buf] + (uint32_t)(row * SAS + ch * 8) * 2,
                     g_ha + (size_t)r * KPAD + kb * 32 + ch * 8, v);
            }
            {
                bool v = (n0 + row) < WN;
                int r = v ? (n0 + row) : 0;
                cp16(bS[buf] + (uint32_t)(row * SAS + ch * 8) * 2,
                     g_bt + (size_t)r * KPAD + kb * 32 + ch * 8, v);
            }
        }
    };

    load_blk(0, 0);
    cp_commit();

    // per-thread ldmatrix row/col offsets
    const int lr = (lid & 7) + ((lid >> 3) & 1) * 8;   // A: row within m16 tile
    const int lk = (lid >> 4) * 8;                      // A: k offset within k16
    const int br = lid & 7;                             // B: row within n8 tile
    const int bk = (lid >> 3) * 8;                      // B: k offset within k32

#pragma unroll 1
    for (int kb = 0; kb < 9; kb++) {
        const int buf = kb & 1;
        if (kb < 8) {
            load_blk(kb + 1, buf ^ 1);
            cp_commit();
            cp_wait<1>();
        } else {
            cp_wait<0>();
        }
        __syncthreads();

        // A fragments: [mt][kk][4]
        uint32_t af[2][2][4];
#pragma unroll
        for (int mt = 0; mt < 2; mt++)
#pragma unroll
            for (int kk = 0; kk < 2; kk++) {
                uint32_t addr = aS[buf] + (uint32_t)((wm * 32 + mt * 16 + lr) * SAS + kk * 16 + lk) * 2;
                ldm_x4(af[mt][kk], addr);
            }
#pragma unroll
        for (int nt = 0; nt < 8; nt++) {
            uint32_t bf[4];
            uint32_t addr = bS[buf] + (uint32_t)((wn * 64 + nt * 8 + br) * SAS + bk) * 2;
            ldm_x4(bf, addr);
#pragma unroll
            for (int kk = 0; kk < 2; kk++)
#pragma unroll
                for (int mt = 0; mt < 2; mt++)
                    mma16816(acc[mt][nt], af[mt][kk], bf[kk * 2], bf[kk * 2 + 1]);
        }
        __syncthreads();
    }

    // epilogue: add bias, store float2 pairs
    const int rbase = m0 + wm * 32;
    const int cbase = n0 + wn * 64;
#pragma unroll
    for (int nt = 0; nt < 8; nt++) {
        int col = cbase + nt * 8 + (lid & 3) * 2;
        if (col + 1 >= WN) continue;
        float2 bb = *(const float2*)(b2 + col);
#pragma unroll
        for (int mt = 0; mt < 2; mt++) {
            int row = rbase + mt * 16 + (lid >> 2);
            float* wp = g_w + (size_t)row * WN + col;
            if (row < E) {
                float2 v0 = make_float2(acc[mt][nt][0] + bb.x, acc[mt][nt][1] + bb.y);
                *(float2*)wp = v0;
            }
            if (row + 8 < E) {
                float2 v1 = make_float2(acc[mt][nt][2] + bb.x, acc[mt][nt][3] + bb.y);
                *(float2*)(wp + (size_t)8 * WN) = v1;
            }
        }
    }
}

// ---------------- per-edge tensor-product epilogue ----------------
__global__ __launch_bounds__(192) void tp_epilogue(const float* __restrict__ node_attr,
                                                   const int* __restrict__ edge_index,
                                                   const float* __restrict__ edge_sh,
                                                   int E) {
    const int e = blockIdx.x;
    if (e >= E) return;
    __shared__ float sx[IN_SIZE];
    __shared__ float sc0e[58];
    __shared__ float sc1o[204];
    __shared__ float sc1e[204];
    __shared__ float sc0o[58];
    __shared__ float ssh[4];
    __shared__ int s_src;

    const int t = threadIdx.x;
    if (t == 0) s_src = edge_index[e];
    if (t < 4) ssh[t] = edge_sh[(size_t)e * 4 + t];
    {
        const int dst = edge_index[E + e];
        const float* xr = node_attr + (size_t)dst * IN_SIZE;
        for (int i = t; i < IN_SIZE; i += 192) sx[i] = xr[i];
    }
    __syncthreads();

    const float sh0 = ssh[0], s1x = ssh[1], s1y = ssh[2], s1z = ssh[3];
    const float inv_s3 = 0.57735026918962576f;
    const float inv_s2 = 0.70710678118654752f;

    if (t < 58) {
        if (t < 48) sc0e[t] = sx[t] * sh0;
        else {
            int b = 48 + (t - 48) * 3;
            sc0e[t] = inv_s3 * (sx[b] * s1x + sx[b + 1] * s1y + sx[b + 2] * s1z);
        }
        if (t < 10) {
            int b = 78 + t * 3;
            sc0o[t] = inv_s3 * (sx[b] * s1x + sx[b + 1] * s1y + sx[b + 2] * s1z);
        } else {
            sc0o[t] = sx[108 + t - 10] * sh0;
        }
    }
    if (t < 68) {
        float v0, v1, v2;
        if (t < 48) {
            float xv = sx[t];
            v0 = xv * s1x; v1 = xv * s1y; v2 = xv * s1z;
        } else if (t < 58) {
            int b = 48 + (t - 48) * 3;
            v0 = sx[b] * sh0; v1 = sx[b + 1] * sh0; v2 = sx[b + 2] * sh0;
        } else {
            int b = 78 + (t - 58) * 3;
            float a0 = sx[b], a1 = sx[b + 1], a2 = sx[b + 2];
            v0 = (a1 * s1z - a2 * s1y) * inv_s2;
            v1 = (a2 * s1x - a0 * s1z) * inv_s2;
            v2 = (a0 * s1y - a1 * s1x) * inv_s2;
        }
        sc1o[t * 3 + 0] = v0; sc1o[t * 3 + 1] = v1; sc1o[t * 3 + 2] = v2;
        if (t < 10) {
            int b = 48 + t * 3;
            float a0 = sx[b], a1 = sx[b + 1], a2 = sx[b + 2];
            v0 = (a1 * s1z - a2 * s1y) * inv_s2;
            v1 = (a2 * s1x - a0 * s1z) * inv_s2;
            v2 = (a0 * s1y - a1 * s1x) * inv_s2;
        } else if (t < 20) {
            int b = 78 + (t - 10) * 3;
            v0 = sx[b] * sh0; v1 = sx[b + 1] * sh0; v2 = sx[b + 2] * sh0;
        } else {
            float xv = sx[108 + (t - 20)];
            v0 = xv * s1x; v1 = xv * s1y; v2 = xv * s1z;
        }
        sc1e[t * 3 + 0] = v0; sc1e[t * 3 + 1] = v1; sc1e[t * 3 + 2] = v2;
    }
    __syncthreads();

    const float* wr = g_w + (size_t)e * WN;
    const float rs58 = 0.13130643285972254f;
    const float rs68 = 0.12126781251816648f;

    if (t < IN_SIZE) {
        float y = 0.0f;
        if (t < 48) {
#pragma unroll
            for (int i = 0; i < 58; i++) y += sc0e[i] * __ldg(wr + OFF_0E + i * 48 + t);
            y *= rs58;
        } else if (t < 108) {
            const float* sc;
            int u, base;
            if (t < 78) { u = t - 48; base = OFF_1O; sc = sc1o; }
            else        { u = t - 78; base = OFF_1E; sc = sc1e; }
            int ov = u / 3;
            int c = u - ov * 3;
#pragma unroll
            for (int i = 0; i < 68; i++) y += sc[i * 3 + c] * __ldg(wr + base + i * 10 + ov);
            y *= rs68;
        } else {
            int oo = t - 108;
#pragma unroll
            for (int i = 0; i < 58; i++) y += sc0o[i] * __ldg(wr + OFF_0O + i * 48 + oo);
            y *= rs58;
        }
        atomicAdd(g_seg + (size_t)s_src * IN_SIZE + t, y);
    }
    if (t == IN_SIZE) atomicAdd(g_cnt + s_src, 1.0f);
}

// ---------------- finalize ----------------
__global__ void finalize_k(const float* __restrict__ node_attr,
                           float* __restrict__ out, int nn) {
    int i = blockIdx.x * blockDim.x + threadIdx.x;
    if (i < nn * IN_SIZE) {
        float c = g_cnt[i / IN_SIZE];
        out[i] = g_seg[i] / fmaxf(c, 1.0f) + node_attr[i];
    }
}

// ---------------- launch ----------------
extern "C" void kernel_launch(void* const* d_in, const int* in_sizes, int n_in,
                              void* d_out, int out_size) {
    const float* node_attr  = (const float*)d_in[0];
    const int*   edge_index = (const int*)d_in[1];
    const float* edge_attr  = (const float*)d_in[2];
    const float* edge_sh    = (const float*)d_in[3];
    const float* W1         = (const float*)d_in[4];
    const float* b1         = (const float*)d_in[5];
    const float* W2         = (const float*)d_in[6];
    const float* b2         = (const float*)d_in[7];
    float* out = (float*)d_out;

    const int E  = in_sizes[2] / HID;
    const int Nn = in_sizes[0] / IN_SIZE;

    zero_k<<<(Nn * IN_SIZE + 255) / 256, 256>>>(Nn);

    // h = relu(edge_attr @ W1 + b1) -> split bf16 into g_ha
    {
        dim3 grid((HID + 63) / 64, (E + 127) / 128);
        hgemm_k<<<grid, 256>>>(edge_attr, W1, b1, E);
    }

    // W2 -> split bf16 transposed g_bt
    convB_k<<<(HID * WN + 255) / 256, 256>>>(W2);

    // w = A' @ B' + b2 on HMMA tensor cores
    {
        dim3 grid((WN + 127) / 128, (E + 127) / 128);
        wgemm_mma<<<grid, 256>>>(b2, E);
    }

    tp_epilogue<<<E, 192>>>(node_attr, edge_index, edge_sh, E);

    finalize_k<<<(Nn * IN_SIZE + 255) / 256, 256>>>(node_attr, out, Nn);
}

// round 4
// speedup vs baseline: 1.8348x; 1.4765x over previous
#include <cuda_runtime.h>
#include <cuda_bf16.h>
#include <math.h>
#include <stdint.h>
#include <stddef.h>

// ---------------- problem constants ----------------
#define IN_SIZE 156          // 48 + 30 + 30 + 48
#define HID 96
#define WN 6928
#define MAX_E 50000
#define MAX_N 10000
#define KPAD 320             // row stride of split-bf16 operands; 288 used + zero pad
#define KUSE 288             // 96(hi) + 96(hi) + 96(lo)

// w segment offsets
#define OFF_0E 0
#define OFF_1O 2784
#define OFF_1E 3464
#define OFF_0O 4144

// ---------------- scratch (device globals; zero-initialized by CUDA) ----------------
__device__ __nv_bfloat16 g_ha[(size_t)(MAX_E + 128) * KPAD];  // A' split bf16
__device__ __nv_bfloat16 g_bt[(size_t)(WN + 128) * KPAD];     // B'^T split bf16 [n][k]
__device__ float g_w[(size_t)MAX_E * WN];
__device__ float g_seg[(size_t)MAX_N * IN_SIZE];
__device__ float g_cnt[MAX_N];

// ---------------- PTX helpers (compute_103-safe only) ----------------
__device__ __forceinline__ uint32_t smem_u32(const void* p) {
    uint32_t a;
    asm("{ .reg .u64 t; cvta.to.shared.u64 t, %1; cvt.u32.u64 %0, t; }" : "=r"(a) : "l"(p));
    return a;
}
__device__ __forceinline__ void cp16(uint32_t d, const void* s, bool v) {
    int sz = v ? 16 : 0;
    asm volatile("cp.async.cg.shared.global [%0], [%1], 16, %2;" :: "r"(d), "l"(s), "r"(sz) : "memory");
}
__device__ __forceinline__ void cp_commit() { asm volatile("cp.async.commit_group;" ::: "memory"); }
template<int N> __device__ __forceinline__ void cp_wait() { asm volatile("cp.async.wait_group %0;" :: "n"(N) : "memory"); }

__device__ __forceinline__ void ldm_x4(uint32_t* r, uint32_t addr) {
    asm volatile("ldmatrix.sync.aligned.m8n8.x4.shared.b16 {%0,%1,%2,%3}, [%4];"
                 : "=r"(r[0]), "=r"(r[1]), "=r"(r[2]), "=r"(r[3]) : "r"(addr));
}
__device__ __forceinline__ void mma16816(float* d, const uint32_t* a, uint32_t b0, uint32_t b1) {
    asm volatile("mma.sync.aligned.m16n8k16.row.col.f32.bf16.bf16.f32 "
                 "{%0,%1,%2,%3}, {%4,%5,%6,%7}, {%8,%9}, {%0,%1,%2,%3};"
                 : "+f"(d[0]), "+f"(d[1]), "+f"(d[2]), "+f"(d[3])
                 : "r"(a[0]), "r"(a[1]), "r"(a[2]), "r"(a[3]), "r"(b0), "r"(b1));
}

// ---------------- zero-init ----------------
__global__ void zero_k(int nn) {
    int i = blockIdx.x * blockDim.x + threadIdx.x;
    int ns = nn * IN_SIZE;
    if (i < ns) g_seg[i] = 0.0f;
    if (i < nn) g_cnt[i] = 0.0f;
}

// ---------------- h GEMM (fp32 SIMT): g_ha = split_bf16(relu(edge_attr@W1 + b1)) ----------------
__global__ __launch_bounds__(256) void hgemm_k(const float* __restrict__ A,
                                               const float* __restrict__ B,
                                               const float* __restrict__ bias,
                                               int M) {
    __shared__ float sA[48 * 132];
    __shared__ float sB[48 * 64];

    const int n0 = blockIdx.x * 64;
    const int m0 = blockIdx.y * 128;
    const int tid = threadIdx.x;
    const int tmi = tid >> 4;
    const int tni = tid & 15;

    float acc[8][4];
#pragma unroll
    for (int mm = 0; mm < 8; mm++)
#pragma unroll
        for (int nn = 0; nn < 4; nn++) acc[mm][nn] = 0.0f;

#pragma unroll
    for (int p = 0; p < 2; p++) {
        const int kb = p * 48;
#pragma unroll
        for (int it = 0; it < 6; it++) {
            int idx = tid + it * 256;
            int e = idx / 12;
            int k4 = idx % 12;
            float4 v = make_float4(0.f, 0.f, 0.f, 0.f);
            if (m0 + e < M)
                v = *(const float4*)(A + (size_t)(m0 + e) * HID + kb + k4 * 4);
            sA[(k4 * 4 + 0) * 132 + e] = v.x;
            sA[(k4 * 4 + 1) * 132 + e] = v.y;
            sA[(k4 * 4 + 2) * 132 + e] = v.z;
            sA[(k4 * 4 + 3) * 132 + e] = v.w;
        }
#pragma unroll
        for (int it = 0; it < 3; it++) {
            int idx = tid + it * 256;
            int k = idx / 16;
            int j4 = idx % 16;
            int j = n0 + j4 * 4;
            float4 v = make_float4(0.f, 0.f, 0.f, 0.f);
            if (j < HID)
                v = *(const float4*)(B + (size_t)(kb + k) * HID + j);
            *(float4*)(sB + k * 64 + j4 * 4) = v;
        }
        __syncthreads();

#pragma unroll 8
        for (int k = 0; k < 48; k++) {
            float4 a0 = *(float4*)(sA + k * 132 + tmi * 8);
            float4 a1 = *(float4*)(sA + k * 132 + tmi * 8 + 4);
            float4 b = *(float4*)(sB + k * 64 + tni * 4);
            float av[8] = {a0.x, a0.y, a0.z, a0.w, a1.x, a1.y, a1.z, a1.w};
            float bv[4] = {b.x, b.y, b.z, b.w};
#pragma unroll
            for (int mm = 0; mm < 8; mm++)
#pragma unroll
                for (int nn = 0; nn < 4; nn++)
                    acc[mm][nn] += av[mm] * bv[nn];
        }
        __syncthreads();
    }

    const int n = n0 + tni * 4;
#pragma unroll
    for (int mm = 0; mm < 8; mm++) {
        int e = m0 + tmi * 8 + mm;
        if (e >= M) continue;
        size_t rb = (size_t)e * KPAD;
#pragma unroll
        for (int nn = 0; nn < 4; nn++) {
            int nc = n + nn;
            if (nc >= HID) continue;
            float v = fmaxf(acc[mm][nn] + bias[nc], 0.0f);
            __nv_bfloat16 hi = __float2bfloat16(v);
            __nv_bfloat16 lo = __float2bfloat16(v - __bfloat162float(hi));
            g_ha[rb + nc] = hi;
            g_ha[rb + 96 + nc] = hi;
            g_ha[rb + 192 + nc] = lo;
        }
    }
}

// ---------------- B' conversion: W2[96][6928] fp32 -> g_bt[6928][320] bf16 ----------------
__global__ void convB_k(const float* __restrict__ W2) {
    int i = blockIdx.x * blockDim.x + threadIdx.x;
    if (i >= HID * WN) return;
    int k = i / WN;
    int n = i - k * WN;
    float v = W2[i];
    __nv_bfloat16 hi = __float2bfloat16(v);
    __nv_bfloat16 lo = __float2bfloat16(v - __bfloat162float(hi));
    size_t rb = (size_t)n * KPAD;
    g_bt[rb + k] = hi;          // pairs with Ah
    g_bt[rb + 96 + k] = lo;     // pairs with Ah
    g_bt[rb + 192 + k] = hi;    // pairs with Al
}

// ---------------- w GEMM via mma.sync (HMMA bf16) ----------------
// 128x128 CTA tile, 8 warps (4M x 2N), warp tile 32x64.
// K = 320 (288 + zero pad) in 5 blocks of 64, double-buffered cp.async.
// __launch_bounds__(256,2) forces <=128 regs -> 2 CTAs/SM for latency hiding.
#define SBS 72               // smem row stride in bf16 (144B: 16B-aligned, conflict-free)
#define STAGE_B (128 * SBS * 2)            // bytes per operand per stage (18432)
#define STAGE_TOT (2 * STAGE_B)            // A + B per stage (36864)
__global__ __launch_bounds__(256, 2) void wgemm_mma(const float* __restrict__ b2, int E) {
    extern __shared__ __align__(16) __nv_bfloat16 smem[];

    const int tid = threadIdx.x;
    const int wid = tid >> 5;
    const int lid = tid & 31;
    const int wm = wid >> 1;     // 0..3 -> rows wm*32
    const int wn = wid & 1;      // 0..1 -> cols wn*64
    const int n0 = blockIdx.x * 128;
    const int m0 = blockIdx.y * 128;

    const uint32_t sb = smem_u32(smem);

    float acc[2][8][4];
#pragma unroll
    for (int mt = 0; mt < 2; mt++)
#pragma unroll
        for (int nt = 0; nt < 8; nt++)
#pragma unroll
            for (int q = 0; q < 4; q++) acc[mt][nt][q] = 0.0f;

    // loader: one K64 block (128B per row) into stage buf
    auto load_blk = [&](int kb, int buf) {
        const uint32_t aB = sb + (uint32_t)buf * STAGE_TOT;
        const uint32_t bB = aB + STAGE_B;
#pragma unroll
        for (int i = 0; i < 8; i++) {
            int idx = tid + i * 256;          // 0..2047
            int row = (idx & 1023) >> 3;
            int ch = idx & 7;
            uint32_t doff = (uint32_t)(row * SBS + ch * 8) * 2;
            if (idx < 1024) {
                bool v = (m0 + row) < E;
                int r = v ? (m0 + row) : 0;
                cp16(aB + doff, g_ha + (size_t)r * KPAD + kb * 64 + ch * 8, v);
            } else {
                bool v = (n0 + row) < WN;
                int r = v ? (n0 + row) : 0;
                cp16(bB + doff, g_bt + (size_t)r * KPAD + kb * 64 + ch * 8, v);
            }
        }
    };

    load_blk(0, 0);
    cp_commit();

    // per-thread ldmatrix offsets
    const int lr = (lid & 7) + ((lid >> 3) & 1) * 8;   // A row within m16
    const int lk = (lid >> 4) * 8;                      // A k offset within k16
    const int br = lid & 7;                             // B row within n8
    const int bk = (lid >> 3) * 8;                      // B k offset within k32

#pragma unroll 1
    for (int kb = 0; kb < 5; kb++) {
        const int buf = kb & 1;
        if (kb < 4) {
            load_blk(kb + 1, buf ^ 1);
            cp_commit();
            cp_wait<1>();
        } else {
            cp_wait<0>();
        }
        __syncthreads();

        const uint32_t aB = sb + (uint32_t)buf * STAGE_TOT;
        const uint32_t bB = aB + STAGE_B;

#pragma unroll
        for (int kh = 0; kh < 2; kh++) {            // two k32 halves
            uint32_t af[2][2][4];
#pragma unroll
            for (int mt = 0; mt < 2; mt++)
#pragma unroll
                for (int kk = 0; kk < 2; kk++) {
                    uint32_t addr = aB + (uint32_t)((wm * 32 + mt * 16 + lr) * SBS + kh * 32 + kk * 16 + lk) * 2;
                    ldm_x4(af[mt][kk], addr);
                }
#pragma unroll
            for (int nt = 0; nt < 8; nt++) {
                uint32_t bf[4];
                uint32_t addr = bB + (uint32_t)((wn * 64 + nt * 8 + br) * SBS + kh * 32 + bk) * 2;
                ldm_x4(bf, addr);
#pragma unroll
                for (int kk = 0; kk < 2; kk++)
#pragma unroll
                    for (int mt = 0; mt < 2; mt++)
                        mma16816(acc[mt][nt], af[mt][kk], bf[kk * 2], bf[kk * 2 + 1]);
            }
        }
        __syncthreads();
    }

    // epilogue: add bias, store float2 pairs
    const int rbase = m0 + wm * 32;
    const int cbase = n0 + wn * 64;
#pragma unroll
    for (int nt = 0; nt < 8; nt++) {
        int col = cbase + nt * 8 + (lid & 3) * 2;
        if (col + 1 >= WN) continue;
        float2 bb = *(const float2*)(b2 + col);
#pragma unroll
        for (int mt = 0; mt < 2; mt++) {
            int row = rbase + mt * 16 + (lid >> 2);
            float* wp = g_w + (size_t)row * WN + col;
            if (row < E) {
                float2 v0 = make_float2(acc[mt][nt][0] + bb.x, acc[mt][nt][1] + bb.y);
                *(float2*)wp = v0;
            }
            if (row + 8 < E) {
                float2 v1 = make_float2(acc[mt][nt][2] + bb.x, acc[mt][nt][3] + bb.y);
                *(float2*)(wp + (size_t)8 * WN) = v1;
            }
        }
    }
}

// ---------------- per-edge tensor-product epilogue ----------------
__global__ __launch_bounds__(192) void tp_epilogue(const float* __restrict__ node_attr,
                                                   const int* __restrict__ edge_index,
                                                   const float* __restrict__ edge_sh,
                                                   int E) {
    const int e = blockIdx.x;
    if (e >= E) return;
    __shared__ float sx[IN_SIZE];
    __shared__ float sc0e[58];
    __shared__ float sc1o[204];
    __shared__ float sc1e[204];
    __shared__ float sc0o[58];
    __shared__ float ssh[4];
    __shared__ int s_src;

    const int t = threadIdx.x;
    if (t == 0) s_src = edge_index[e];
    if (t < 4) ssh[t] = edge_sh[(size_t)e * 4 + t];
    {
        const int dst = edge_index[E + e];
        const float* xr = node_attr + (size_t)dst * IN_SIZE;
        for (int i = t; i < IN_SIZE; i += 192) sx[i] = xr[i];
    }
    __syncthreads();

    const float sh0 = ssh[0], s1x = ssh[1], s1y = ssh[2], s1z = ssh[3];
    const float inv_s3 = 0.57735026918962576f;
    const float inv_s2 = 0.70710678118654752f;

    if (t < 58) {
        if (t < 48) sc0e[t] = sx[t] * sh0;
        else {
            int b = 48 + (t - 48) * 3;
            sc0e[t] = inv_s3 * (sx[b] * s1x + sx[b + 1] * s1y + sx[b + 2] * s1z);
        }
        if (t < 10) {
            int b = 78 + t * 3;
            sc0o[t] = inv_s3 * (sx[b] * s1x + sx[b + 1] * s1y + sx[b + 2] * s1z);
        } else {
            sc0o[t] = sx[108 + t - 10] * sh0;
        }
    }
    if (t < 68) {
        float v0, v1, v2;
        if (t < 48) {
            float xv = sx[t];
            v0 = xv * s1x; v1 = xv * s1y; v2 = xv * s1z;
        } else if (t < 58) {
            int b = 48 + (t - 48) * 3;
            v0 = sx[b] * sh0; v1 = sx[b + 1] * sh0; v2 = sx[b + 2] * sh0;
        } else {
            int b = 78 + (t - 58) * 3;
            float a0 = sx[b], a1 = sx[b + 1], a2 = sx[b + 2];
            v0 = (a1 * s1z - a2 * s1y) * inv_s2;
            v1 = (a2 * s1x - a0 * s1z) * inv_s2;
            v2 = (a0 * s1y - a1 * s1x) * inv_s2;
        }
        sc1o[t * 3 + 0] = v0; sc1o[t * 3 + 1] = v1; sc1o[t * 3 + 2] = v2;
        if (t < 10) {
            int b = 48 + t * 3;
            float a0 = sx[b], a1 = sx[b + 1], a2 = sx[b + 2];
            v0 = (a1 * s1z - a2 * s1y) * inv_s2;
            v1 = (a2 * s1x - a0 * s1z) * inv_s2;
            v2 = (a0 * s1y - a1 * s1x) * inv_s2;
        } else if (t < 20) {
            int b = 78 + (t - 10) * 3;
            v0 = sx[b] * sh0; v1 = sx[b + 1] * sh0; v2 = sx[b + 2] * sh0;
        } else {
            float xv = sx[108 + (t - 20)];
            v0 = xv * s1x; v1 = xv * s1y; v2 = xv * s1z;
        }
        sc1e[t * 3 + 0] = v0; sc1e[t * 3 + 1] = v1; sc1e[t * 3 + 2] = v2;
    }
    __syncthreads();

    const float* wr = g_w + (size_t)e * WN;
    const float rs58 = 0.13130643285972254f;
    const float rs68 = 0.12126781251816648f;

    if (t < IN_SIZE) {
        float y = 0.0f;
        if (t < 48) {
#pragma unroll
            for (int i = 0; i < 58; i++) y += sc0e[i] * __ldg(wr + OFF_0E + i * 48 + t);
            y *= rs58;
        } else if (t < 108) {
            const float* sc;
            int u, base;
            if (t < 78) { u = t - 48; base = OFF_1O; sc = sc1o; }
            else        { u = t - 78; base = OFF_1E; sc = sc1e; }
            int ov = u / 3;
            int c = u - ov * 3;
#pragma unroll
            for (int i = 0; i < 68; i++) y += sc[i * 3 + c] * __ldg(wr + base + i * 10 + ov);
            y *= rs68;
        } else {
            int oo = t - 108;
#pragma unroll
            for (int i = 0; i < 58; i++) y += sc0o[i] * __ldg(wr + OFF_0O + i * 48 + oo);
            y *= rs58;
        }
        atomicAdd(g_seg + (size_t)s_src * IN_SIZE + t, y);
    }
    if (t == IN_SIZE) atomicAdd(g_cnt + s_src, 1.0f);
}

// ---------------- finalize ----------------
__global__ void finalize_k(const float* __restrict__ node_attr,
                           float* __restrict__ out, int nn) {
    int i = blockIdx.x * blockDim.x + threadIdx.x;
    if (i < nn * IN_SIZE) {
        float c = g_cnt[i / IN_SIZE];
        out[i] = g_seg[i] / fmaxf(c, 1.0f) + node_attr[i];
    }
}

// ---------------- launch ----------------
extern "C" void kernel_launch(void* const* d_in, const int* in_sizes, int n_in,
                              void* d_out, int out_size) {
    const float* node_attr  = (const float*)d_in[0];
    const int*   edge_index = (const int*)d_in[1];
    const float* edge_attr  = (const float*)d_in[2];
    const float* edge_sh    = (const float*)d_in[3];
    const float* W1         = (const float*)d_in[4];
    const float* b1         = (const float*)d_in[5];
    const float* W2         = (const float*)d_in[6];
    const float* b2         = (const float*)d_in[7];
    float* out = (float*)d_out;

    const int E  = in_sizes[2] / HID;
    const int Nn = in_sizes[0] / IN_SIZE;

    zero_k<<<(Nn * IN_SIZE + 255) / 256, 256>>>(Nn);

    // h = relu(edge_attr @ W1 + b1) -> split bf16 into g_ha
    {
        dim3 grid((HID + 63) / 64, (E + 127) / 128);
        hgemm_k<<<grid, 256>>>(edge_attr, W1, b1, E);
    }

    // W2 -> split bf16 transposed g_bt
    convB_k<<<(HID * WN + 255) / 256, 256>>>(W2);

    // w = A' @ B' + b2 on HMMA tensor cores
    {
        const int dyn = 2 * STAGE_TOT;   // 73728 bytes
        cudaFuncSetAttribute(wgemm_mma, cudaFuncAttributeMaxDynamicSharedMemorySize, dyn);
        dim3 grid((WN + 127) / 128, (E + 127) / 128);
        wgemm_mma<<<grid, 256, dyn>>>(b2, E);
    }

    tp_epilogue<<<E, 192>>>(node_attr, edge_index, edge_sh, E);

    finalize_k<<<(Nn * IN_SIZE + 255) / 256, 256>>>(node_attr, out, Nn);
}

// round 5
// speedup vs baseline: 1.9703x; 1.0738x over previous
#include <cuda_runtime.h>
#include <cuda_bf16.h>
#include <cuda_fp16.h>
#include <math.h>
#include <stdint.h>
#include <stddef.h>

// ---------------- problem constants ----------------
#define IN_SIZE 156          // 48 + 30 + 30 + 48
#define HID 96
#define WN 6928
#define MAX_E 50000
#define MAX_N 10000
#define KPAD 320             // row stride of split-bf16 operands; 288 used + zero pad
#define KUSE 288             // 96(hi) + 96(hi) + 96(lo)

// w segment offsets
#define OFF_0E 0
#define OFF_1O 2784
#define OFF_1E 3464
#define OFF_0O 4144

// ---------------- scratch (device globals; zero-initialized by CUDA) ----------------
__device__ __nv_bfloat16 g_ha[(size_t)(MAX_E + 128) * KPAD];  // A' split bf16
__device__ __nv_bfloat16 g_bt[(size_t)(WN + 128) * KPAD];     // B'^T split bf16 [n][k]
__device__ __half g_w[(size_t)MAX_E * WN];                    // w in fp16 (halves traffic)
__device__ float g_seg[(size_t)MAX_N * IN_SIZE];
__device__ float g_cnt[MAX_N];

// ---------------- PTX helpers (compute_103-safe only) ----------------
__device__ __forceinline__ uint32_t smem_u32(const void* p) {
    uint32_t a;
    asm("{ .reg .u64 t; cvta.to.shared.u64 t, %1; cvt.u32.u64 %0, t; }" : "=r"(a) : "l"(p));
    return a;
}
__device__ __forceinline__ void cp16(uint32_t d, const void* s, bool v) {
    int sz = v ? 16 : 0;
    asm volatile("cp.async.cg.shared.global [%0], [%1], 16, %2;" :: "r"(d), "l"(s), "r"(sz) : "memory");
}
__device__ __forceinline__ void cp_commit() { asm volatile("cp.async.commit_group;" ::: "memory"); }
template<int N> __device__ __forceinline__ void cp_wait() { asm volatile("cp.async.wait_group %0;" :: "n"(N) : "memory"); }

__device__ __forceinline__ void ldm_x4(uint32_t* r, uint32_t addr) {
    asm volatile("ldmatrix.sync.aligned.m8n8.x4.shared.b16 {%0,%1,%2,%3}, [%4];"
                 : "=r"(r[0]), "=r"(r[1]), "=r"(r[2]), "=r"(r[3]) : "r"(addr));
}
__device__ __forceinline__ void mma16816(float* d, const uint32_t* a, uint32_t b0, uint32_t b1) {
    asm volatile("mma.sync.aligned.m16n8k16.row.col.f32.bf16.bf16.f32 "
                 "{%0,%1,%2,%3}, {%4,%5,%6,%7}, {%8,%9}, {%0,%1,%2,%3};"
                 : "+f"(d[0]), "+f"(d[1]), "+f"(d[2]), "+f"(d[3])
                 : "r"(a[0]), "r"(a[1]), "r"(a[2]), "r"(a[3]), "r"(b0), "r"(b1));
}

// ---------------- zero-init ----------------
__global__ void zero_k(int nn) {
    int i = blockIdx.x * blockDim.x + threadIdx.x;
    int ns = nn * IN_SIZE;
    if (i < ns) g_seg[i] = 0.0f;
    if (i < nn) g_cnt[i] = 0.0f;
}

// ---------------- h GEMM (fp32 SIMT): g_ha = split_bf16(relu(edge_attr@W1 + b1)) ----------------
__global__ __launch_bounds__(256) void hgemm_k(const float* __restrict__ A,
                                               const float* __restrict__ B,
                                               const float* __restrict__ bias,
                                               int M) {
    __shared__ float sA[48 * 132];
    __shared__ float sB[48 * 64];

    const int n0 = blockIdx.x * 64;
    const int m0 = blockIdx.y * 128;
    const int tid = threadIdx.x;
    const int tmi = tid >> 4;
    const int tni = tid & 15;

    float acc[8][4];
#pragma unroll
    for (int mm = 0; mm < 8; mm++)
#pragma unroll
        for (int nn = 0; nn < 4; nn++) acc[mm][nn] = 0.0f;

#pragma unroll
    for (int p = 0; p < 2; p++) {
        const int kb = p * 48;
#pragma unroll
        for (int it = 0; it < 6; it++) {
            int idx = tid + it * 256;
            int e = idx / 12;
            int k4 = idx % 12;
            float4 v = make_float4(0.f, 0.f, 0.f, 0.f);
            if (m0 + e < M)
                v = *(const float4*)(A + (size_t)(m0 + e) * HID + kb + k4 * 4);
            sA[(k4 * 4 + 0) * 132 + e] = v.x;
            sA[(k4 * 4 + 1) * 132 + e] = v.y;
            sA[(k4 * 4 + 2) * 132 + e] = v.z;
            sA[(k4 * 4 + 3) * 132 + e] = v.w;
        }
#pragma unroll
        for (int it = 0; it < 3; it++) {
            int idx = tid + it * 256;
            int k = idx / 16;
            int j4 = idx % 16;
            int j = n0 + j4 * 4;
            float4 v = make_float4(0.f, 0.f, 0.f, 0.f);
            if (j < HID)
                v = *(const float4*)(B + (size_t)(kb + k) * HID + j);
            *(float4*)(sB + k * 64 + j4 * 4) = v;
        }
        __syncthreads();

#pragma unroll 8
        for (int k = 0; k < 48; k++) {
            float4 a0 = *(float4*)(sA + k * 132 + tmi * 8);
            float4 a1 = *(float4*)(sA + k * 132 + tmi * 8 + 4);
            float4 b = *(float4*)(sB + k * 64 + tni * 4);
            float av[8] = {a0.x, a0.y, a0.z, a0.w, a1.x, a1.y, a1.z, a1.w};
            float bv[4] = {b.x, b.y, b.z, b.w};
#pragma unroll
            for (int mm = 0; mm < 8; mm++)
#pragma unroll
                for (int nn = 0; nn < 4; nn++)
                    acc[mm][nn] += av[mm] * bv[nn];
        }
        __syncthreads();
    }

    const int n = n0 + tni * 4;
#pragma unroll
    for (int mm = 0; mm < 8; mm++) {
        int e = m0 + tmi * 8 + mm;
        if (e >= M) continue;
        size_t rb = (size_t)e * KPAD;
#pragma unroll
        for (int nn = 0; nn < 4; nn++) {
            int nc = n + nn;
            if (nc >= HID) continue;
            float v = fmaxf(acc[mm][nn] + bias[nc], 0.0f);
            __nv_bfloat16 hi = __float2bfloat16(v);
            __nv_bfloat16 lo = __float2bfloat16(v - __bfloat162float(hi));
            g_ha[rb + nc] = hi;
            g_ha[rb + 96 + nc] = hi;
            g_ha[rb + 192 + nc] = lo;
        }
    }
}

// ---------------- B' conversion: W2[96][6928] fp32 -> g_bt[6928][320] bf16 ----------------
__global__ void convB_k(const float* __restrict__ W2) {
    int i = blockIdx.x * blockDim.x + threadIdx.x;
    if (i >= HID * WN) return;
    int k = i / WN;
    int n = i - k * WN;
    float v = W2[i];
    __nv_bfloat16 hi = __float2bfloat16(v);
    __nv_bfloat16 lo = __float2bfloat16(v - __bfloat162float(hi));
    size_t rb = (size_t)n * KPAD;
    g_bt[rb + k] = hi;          // pairs with Ah
    g_bt[rb + 96 + k] = lo;     // pairs with Ah
    g_bt[rb + 192 + k] = hi;    // pairs with Al
}

// ---------------- w GEMM via mma.sync (HMMA bf16) ----------------
// 128x128 CTA tile, 4 warps (2M x 2N), warp tile 64x64 (2x reuse vs 32x64).
// K = 320 (288 + zero pad) in 5 blocks of 64, double-buffered cp.async, 2 CTAs/SM.
#define SBS 72               // smem row stride in bf16 (144B: 16B-aligned, conflict-free)
#define STAGE_B (128 * SBS * 2)            // bytes per operand per stage (18432)
#define STAGE_TOT (2 * STAGE_B)            // A + B per stage (36864)
__global__ __launch_bounds__(128, 2) void wgemm_mma(const float* __restrict__ b2, int E) {
    extern __shared__ __align__(16) __nv_bfloat16 smem[];

    const int tid = threadIdx.x;
    const int wid = tid >> 5;
    const int lid = tid & 31;
    const int wm = wid >> 1;     // 0..1 -> rows wm*64
    const int wn = wid & 1;      // 0..1 -> cols wn*64
    const int n0 = blockIdx.x * 128;
    const int m0 = blockIdx.y * 128;

    const uint32_t sb = smem_u32(smem);

    float acc[4][8][4];
#pragma unroll
    for (int mt = 0; mt < 4; mt++)
#pragma unroll
        for (int nt = 0; nt < 8; nt++)
#pragma unroll
            for (int q = 0; q < 4; q++) acc[mt][nt][q] = 0.0f;

    // loader: one K64 block (128B per row) into stage buf (128 threads x 16 chunks)
    auto load_blk = [&](int kb, int buf) {
        const uint32_t aB = sb + (uint32_t)buf * STAGE_TOT;
        const uint32_t bB = aB + STAGE_B;
#pragma unroll
        for (int i = 0; i < 16; i++) {
            int idx = tid + i * 128;          // 0..2047
            int row = (idx & 1023) >> 3;
            int ch = idx & 7;
            uint32_t doff = (uint32_t)(row * SBS + ch * 8) * 2;
            if (idx < 1024) {
                bool v = (m0 + row) < E;
                int r = v ? (m0 + row) : 0;
                cp16(aB + doff, g_ha + (size_t)r * KPAD + kb * 64 + ch * 8, v);
            } else {
                bool v = (n0 + row) < WN;
                int r = v ? (n0 + row) : 0;
                cp16(bB + doff, g_bt + (size_t)r * KPAD + kb * 64 + ch * 8, v);
            }
        }
    };

    load_blk(0, 0);
    cp_commit();

    // per-thread ldmatrix offsets
    const int lr = (lid & 7) + ((lid >> 3) & 1) * 8;   // A row within m16
    const int lk = (lid >> 4) * 8;                      // A k offset within k16
    const int br = lid & 7;                             // B row within n8
    const int bk = (lid >> 3) * 8;                      // B k offset within k32

#pragma unroll 1
    for (int kb = 0; kb < 5; kb++) {
        const int buf = kb & 1;
        if (kb < 4) {
            load_blk(kb + 1, buf ^ 1);
            cp_commit();
            cp_wait<1>();
        } else {
            cp_wait<0>();
        }
        __syncthreads();

        const uint32_t aB = sb + (uint32_t)buf * STAGE_TOT;
        const uint32_t bB = aB + STAGE_B;

#pragma unroll
        for (int kh = 0; kh < 2; kh++) {            // two k32 halves
            uint32_t af[4][2][4];
#pragma unroll
            for (int mt = 0; mt < 4; mt++)
#pragma unroll
                for (int kk = 0; kk < 2; kk++) {
                    uint32_t addr = aB + (uint32_t)((wm * 64 + mt * 16 + lr) * SBS + kh * 32 + kk * 16 + lk) * 2;
                    ldm_x4(af[mt][kk], addr);
                }
#pragma unroll
            for (int nt = 0; nt < 8; nt++) {
                uint32_t bf[4];
                uint32_t addr = bB + (uint32_t)((wn * 64 + nt * 8 + br) * SBS + kh * 32 + bk) * 2;
                ldm_x4(bf, addr);
#pragma unroll
                for (int kk = 0; kk < 2; kk++)
#pragma unroll
                    for (int mt = 0; mt < 4; mt++)
                        mma16816(acc[mt][nt], af[mt][kk], bf[kk * 2], bf[kk * 2 + 1]);
            }
        }
        __syncthreads();
    }

    // epilogue: add bias, store half2 pairs
    const int rbase = m0 + wm * 64;
    const int cbase = n0 + wn * 64;
#pragma unroll
    for (int nt = 0; nt < 8; nt++) {
        int col = cbase + nt * 8 + (lid & 3) * 2;
        if (col + 1 >= WN) continue;
        float2 bb = *(const float2*)(b2 + col);
#pragma unroll
        for (int mt = 0; mt < 4; mt++) {
            int row = rbase + mt * 16 + (lid >> 2);
            __half* wp = g_w + (size_t)row * WN + col;
            if (row < E)
                *(__half2*)wp = __floats2half2_rn(acc[mt][nt][0] + bb.x, acc[mt][nt][1] + bb.y);
            if (row + 8 < E)
                *(__half2*)(wp + (size_t)8 * WN) = __floats2half2_rn(acc[mt][nt][2] + bb.x, acc[mt][nt][3] + bb.y);
        }
    }
}

// ---------------- per-edge tensor-product epilogue ----------------
__global__ __launch_bounds__(192) void tp_epilogue(const float* __restrict__ node_attr,
                                                   const int* __restrict__ edge_index,
                                                   const float* __restrict__ edge_sh,
                                                   int E) {
    const int e = blockIdx.x;
    if (e >= E) return;
    __shared__ float sx[IN_SIZE];
    __shared__ float sc0e[58];
    __shared__ float sc1o[204];
    __shared__ float sc1e[204];
    __shared__ float sc0o[58];
    __shared__ float ssh[4];
    __shared__ int s_src;

    const int t = threadIdx.x;
    if (t == 0) s_src = edge_index[e];
    if (t < 4) ssh[t] = edge_sh[(size_t)e * 4 + t];
    {
        const int dst = edge_index[E + e];
        const float* xr = node_attr + (size_t)dst * IN_SIZE;
        for (int i = t; i < IN_SIZE; i += 192) sx[i] = xr[i];
    }
    __syncthreads();

    const float sh0 = ssh[0], s1x = ssh[1], s1y = ssh[2], s1z = ssh[3];
    const float inv_s3 = 0.57735026918962576f;
    const float inv_s2 = 0.70710678118654752f;

    if (t < 58) {
        if (t < 48) sc0e[t] = sx[t] * sh0;
        else {
            int b = 48 + (t - 48) * 3;
            sc0e[t] = inv_s3 * (sx[b] * s1x + sx[b + 1] * s1y + sx[b + 2] * s1z);
        }
        if (t < 10) {
            int b = 78 + t * 3;
            sc0o[t] = inv_s3 * (sx[b] * s1x + sx[b + 1] * s1y + sx[b + 2] * s1z);
        } else {
            sc0o[t] = sx[108 + t - 10] * sh0;
        }
    }
    if (t < 68) {
        float v0, v1, v2;
        if (t < 48) {
            float xv = sx[t];
            v0 = xv * s1x; v1 = xv * s1y; v2 = xv * s1z;
        } else if (t < 58) {
            int b = 48 + (t - 48) * 3;
            v0 = sx[b] * sh0; v1 = sx[b + 1] * sh0; v2 = sx[b + 2] * sh0;
        } else {
            int b = 78 + (t - 58) * 3;
            float a0 = sx[b], a1 = sx[b + 1], a2 = sx[b + 2];
            v0 = (a1 * s1z - a2 * s1y) * inv_s2;
            v1 = (a2 * s1x - a0 * s1z) * inv_s2;
            v2 = (a0 * s1y - a1 * s1x) * inv_s2;
        }
        sc1o[t * 3 + 0] = v0; sc1o[t * 3 + 1] = v1; sc1o[t * 3 + 2] = v2;
        if (t < 10) {
            int b = 48 + t * 3;
            float a0 = sx[b], a1 = sx[b + 1], a2 = sx[b + 2];
            v0 = (a1 * s1z - a2 * s1y) * inv_s2;
            v1 = (a2 * s1x - a0 * s1z) * inv_s2;
            v2 = (a0 * s1y - a1 * s1x) * inv_s2;
        } else if (t < 20) {
            int b = 78 + (t - 10) * 3;
            v0 = sx[b] * sh0; v1 = sx[b + 1] * sh0; v2 = sx[b + 2] * sh0;
        } else {
            float xv = sx[108 + (t - 20)];
            v0 = xv * s1x; v1 = xv * s1y; v2 = xv * s1z;
        }
        sc1e[t * 3 + 0] = v0; sc1e[t * 3 + 1] = v1; sc1e[t * 3 + 2] = v2;
    }
    __syncthreads();

    const __half* wr = g_w + (size_t)e * WN;
    const float rs58 = 0.13130643285972254f;
    const float rs68 = 0.12126781251816648f;

    if (t < IN_SIZE) {
        float y = 0.0f;
        if (t < 48) {
#pragma unroll
            for (int i = 0; i < 58; i++)
                y += sc0e[i] * __half2float(__ldg(wr + OFF_0E + i * 48 + t));
            y *= rs58;
        } else if (t < 108) {
            const float* sc;
            int u, base;
            if (t < 78) { u = t - 48; base = OFF_1O; sc = sc1o; }
            else        { u = t - 78; base = OFF_1E; sc = sc1e; }
            int ov = u / 3;
            int c = u - ov * 3;
#pragma unroll
            for (int i = 0; i < 68; i++)
                y += sc[i * 3 + c] * __half2float(__ldg(wr + base + i * 10 + ov));
            y *= rs68;
        } else {
            int oo = t - 108;
#pragma unroll
            for (int i = 0; i < 58; i++)
                y += sc0o[i] * __half2float(__ldg(wr + OFF_0O + i * 48 + oo));
            y *= rs58;
        }
        atomicAdd(g_seg + (size_t)s_src * IN_SIZE + t, y);
    }
    if (t == IN_SIZE) atomicAdd(g_cnt + s_src, 1.0f);
}

// ---------------- finalize ----------------
__global__ void finalize_k(const float* __restrict__ node_attr,
                           float* __restrict__ out, int nn) {
    int i = blockIdx.x * blockDim.x + threadIdx.x;
    if (i < nn * IN_SIZE) {
        float c = g_cnt[i / IN_SIZE];
        out[i] = g_seg[i] / fmaxf(c, 1.0f) + node_attr[i];
    }
}

// ---------------- launch ----------------
extern "C" void kernel_launch(void* const* d_in, const int* in_sizes, int n_in,
                              void* d_out, int out_size) {
    const float* node_attr  = (const float*)d_in[0];
    const int*   edge_index = (const int*)d_in[1];
    const float* edge_attr  = (const float*)d_in[2];
    const float* edge_sh    = (const float*)d_in[3];
    const float* W1         = (const float*)d_in[4];
    const float* b1         = (const float*)d_in[5];
    const float* W2         = (const float*)d_in[6];
    const float* b2         = (const float*)d_in[7];
    float* out = (float*)d_out;

    const int E  = in_sizes[2] / HID;
    const int Nn = in_sizes[0] / IN_SIZE;

    zero_k<<<(Nn * IN_SIZE + 255) / 256, 256>>>(Nn);

    // h = relu(edge_attr @ W1 + b1) -> split bf16 into g_ha
    {
        dim3 grid((HID + 63) / 64, (E + 127) / 128);
        hgemm_k<<<grid, 256>>>(edge_attr, W1, b1, E);
    }

    // W2 -> split bf16 transposed g_bt
    convB_k<<<(HID * WN + 255) / 256, 256>>>(W2);

    // w = A' @ B' + b2 on HMMA tensor cores (fp16 output)
    {
        const int dyn = 2 * STAGE_TOT;   // 73728 bytes
        cudaFuncSetAttribute(wgemm_mma, cudaFuncAttributeMaxDynamicSharedMemorySize, dyn);
        dim3 grid((WN + 127) / 128, (E + 127) / 128);
        wgemm_mma<<<grid, 128, dyn>>>(b2, E);
    }

    tp_epilogue<<<E, 192>>>(node_attr, edge_index, edge_sh, E);

    finalize_k<<<(Nn * IN_SIZE + 255) / 256, 256>>>(node_attr, out, Nn);
}

// round 6
// speedup vs baseline: 2.5631x; 1.3009x over previous
#include <cuda_runtime.h>
#include <cuda_fp16.h>
#include <math.h>
#include <stdint.h>
#include <stddef.h>

// ---------------- problem constants ----------------
#define IN_SIZE 156          // 48 + 30 + 30 + 48
#define HID 96
#define WN 6928
#define MAX_E 50000
#define MAX_N 10000

// w segment offsets
#define OFF_0E 0
#define OFF_1O 2784
#define OFF_1E 3464
#define OFF_0O 4144

// ---------------- scratch (device globals) ----------------
__device__ float g_ha[(size_t)(MAX_E + 128) * HID];   // h, tf32-rounded fp32
__device__ float g_bt[(size_t)(WN + 128) * HID];      // W2^T, tf32-rounded fp32 [n][k]
__device__ __half g_w[(size_t)MAX_E * WN];            // w in fp16
__device__ float g_seg[(size_t)MAX_N * IN_SIZE];
__device__ float g_cnt[MAX_N];

// ---------------- PTX helpers (compute_103-safe) ----------------
__device__ __forceinline__ uint32_t smem_u32(const void* p) {
    uint32_t a;
    asm("{ .reg .u64 t; cvta.to.shared.u64 t, %1; cvt.u32.u64 %0, t; }" : "=r"(a) : "l"(p));
    return a;
}
__device__ __forceinline__ void cp16(uint32_t d, const void* s, bool v) {
    int sz = v ? 16 : 0;
    asm volatile("cp.async.cg.shared.global [%0], [%1], 16, %2;" :: "r"(d), "l"(s), "r"(sz) : "memory");
}
__device__ __forceinline__ void cp_commit() { asm volatile("cp.async.commit_group;" ::: "memory"); }
template<int N> __device__ __forceinline__ void cp_wait() { asm volatile("cp.async.wait_group %0;" :: "n"(N) : "memory"); }

__device__ __forceinline__ void ldm_x4(uint32_t* r, uint32_t addr) {
    asm volatile("ldmatrix.sync.aligned.m8n8.x4.shared.b16 {%0,%1,%2,%3}, [%4];"
                 : "=r"(r[0]), "=r"(r[1]), "=r"(r[2]), "=r"(r[3]) : "r"(addr));
}
__device__ __forceinline__ void mma_tf32(float* d, const uint32_t* a, uint32_t b0, uint32_t b1) {
    asm volatile("mma.sync.aligned.m16n8k8.row.col.f32.tf32.tf32.f32 "
                 "{%0,%1,%2,%3}, {%4,%5,%6,%7}, {%8,%9}, {%0,%1,%2,%3};"
                 : "+f"(d[0]), "+f"(d[1]), "+f"(d[2]), "+f"(d[3])
                 : "r"(a[0]), "r"(a[1]), "r"(a[2]), "r"(a[3]), "r"(b0), "r"(b1));
}
__device__ __forceinline__ float f2tf32(float f) {
    uint32_t r;
    asm("cvt.rna.tf32.f32 %0, %1;" : "=r"(r) : "f"(f));
    return __uint_as_float(r);
}

// ---------------- zero-init ----------------
__global__ void zero_k(int nn) {
    int i = blockIdx.x * blockDim.x + threadIdx.x;
    int ns = nn * IN_SIZE;
    if (i < ns) g_seg[i] = 0.0f;
    if (i < nn) g_cnt[i] = 0.0f;
}

// ---------------- h GEMM (fp32 SIMT): g_ha = tf32(relu(edge_attr@W1 + b1)) ----------------
__global__ __launch_bounds__(256) void hgemm_k(const float* __restrict__ A,
                                               const float* __restrict__ B,
                                               const float* __restrict__ bias,
                                               int M) {
    __shared__ float sA[48 * 132];
    __shared__ float sB[48 * 64];

    const int n0 = blockIdx.x * 64;
    const int m0 = blockIdx.y * 128;
    const int tid = threadIdx.x;
    const int tmi = tid >> 4;
    const int tni = tid & 15;

    float acc[8][4];
#pragma unroll
    for (int mm = 0; mm < 8; mm++)
#pragma unroll
        for (int nn = 0; nn < 4; nn++) acc[mm][nn] = 0.0f;

#pragma unroll
    for (int p = 0; p < 2; p++) {
        const int kb = p * 48;
#pragma unroll
        for (int it = 0; it < 6; it++) {
            int idx = tid + it * 256;
            int e = idx / 12;
            int k4 = idx % 12;
            float4 v = make_float4(0.f, 0.f, 0.f, 0.f);
            if (m0 + e < M)
                v = *(const float4*)(A + (size_t)(m0 + e) * HID + kb + k4 * 4);
            sA[(k4 * 4 + 0) * 132 + e] = v.x;
            sA[(k4 * 4 + 1) * 132 + e] = v.y;
            sA[(k4 * 4 + 2) * 132 + e] = v.z;
            sA[(k4 * 4 + 3) * 132 + e] = v.w;
        }
#pragma unroll
        for (int it = 0; it < 3; it++) {
            int idx = tid + it * 256;
            int k = idx / 16;
            int j4 = idx % 16;
            int j = n0 + j4 * 4;
            float4 v = make_float4(0.f, 0.f, 0.f, 0.f);
            if (j < HID)
                v = *(const float4*)(B + (size_t)(kb + k) * HID + j);
            *(float4*)(sB + k * 64 + j4 * 4) = v;
        }
        __syncthreads();

#pragma unroll 8
        for (int k = 0; k < 48; k++) {
            float4 a0 = *(float4*)(sA + k * 132 + tmi * 8);
            float4 a1 = *(float4*)(sA + k * 132 + tmi * 8 + 4);
            float4 b = *(float4*)(sB + k * 64 + tni * 4);
            float av[8] = {a0.x, a0.y, a0.z, a0.w, a1.x, a1.y, a1.z, a1.w};
            float bv[4] = {b.x, b.y, b.z, b.w};
#pragma unroll
            for (int mm = 0; mm < 8; mm++)
#pragma unroll
                for (int nn = 0; nn < 4; nn++)
                    acc[mm][nn] += av[mm] * bv[nn];
        }
        __syncthreads();
    }

    const int n = n0 + tni * 4;
#pragma unroll
    for (int mm = 0; mm < 8; mm++) {
        int e = m0 + tmi * 8 + mm;
        if (e >= M) continue;
        size_t rb = (size_t)e * HID;
#pragma unroll
        for (int nn = 0; nn < 4; nn++) {
            int nc = n + nn;
            if (nc >= HID) continue;
            float v = fmaxf(acc[mm][nn] + bias[nc], 0.0f);
            g_ha[rb + nc] = f2tf32(v);
        }
    }
}

// ---------------- B conversion: W2[96][6928] fp32 -> g_bt[6928][96] tf32 ----------------
__global__ void convB_k(const float* __restrict__ W2) {
    int i = blockIdx.x * blockDim.x + threadIdx.x;
    if (i >= HID * WN) return;
    int k = i / WN;
    int n = i - k * WN;
    g_bt[(size_t)n * HID + k] = f2tf32(W2[i]);
}

// ---------------- w GEMM via mma.sync tf32 (K=96, no split) ----------------
// 128x128 CTA tile, 4 warps (2M x 2N), warp tile 64x64. Single-stage full-K smem.
// Row stride 100 floats (400B) -> conflict-free ldmatrix phases. 2 CTAs/SM.
#define ASTR 100                 // smem row stride in floats
#define OPER_B (128 * ASTR * 4)  // bytes per operand (51200)
__global__ __launch_bounds__(128, 2) void wgemm_mma(const float* __restrict__ b2, int E) {
    extern __shared__ __align__(16) float smem[];

    const int tid = threadIdx.x;
    const int wid = tid >> 5;
    const int lid = tid & 31;
    const int wm = wid >> 1;     // 0..1 -> rows wm*64
    const int wn = wid & 1;      // 0..1 -> cols wn*64
    const int n0 = blockIdx.x * 128;
    const int m0 = blockIdx.y * 128;

    const uint32_t aB = smem_u32(smem);
    const uint32_t bB = aB + OPER_B;

    // load full K=96 for A(128 rows) and B(128 rows): 6144 x 16B chunks
#pragma unroll
    for (int i = 0; i < 48; i++) {
        int idx = tid + i * 128;          // 0..6143
        if (idx < 3072) {
            int row = idx / 24, ch = idx % 24;
            bool v = (m0 + row) < E;
            int r = v ? (m0 + row) : 0;
            cp16(aB + (uint32_t)(row * 400 + ch * 16), g_ha + (size_t)r * HID + ch * 4, v);
        } else {
            int l = idx - 3072;
            int row = l / 24, ch = l % 24;
            bool v = (n0 + row) < WN;
            int r = v ? (n0 + row) : 0;
            cp16(bB + (uint32_t)(row * 400 + ch * 16), g_bt + (size_t)r * HID + ch * 4, v);
        }
    }
    cp_commit();

    float acc[4][8][4];
#pragma unroll
    for (int mt = 0; mt < 4; mt++)
#pragma unroll
        for (int nt = 0; nt < 8; nt++)
#pragma unroll
            for (int q = 0; q < 4; q++) acc[mt][nt][q] = 0.0f;

    // per-lane ldmatrix addressing (tf32: 8x8 b16 tile == 8x4 tf32 tile)
    const uint32_t a_row = (uint32_t)(wm * 64 + (lid & 15));
    const uint32_t a_cb  = (uint32_t)((lid >> 4) * 16);            // byte col offset
    const uint32_t b_row = (uint32_t)(wn * 64 + (lid & 7) + ((lid >> 4) << 3));
    const uint32_t b_cb  = (uint32_t)(((lid >> 3) & 1) * 16);

    cp_wait<0>();
    __syncthreads();

#pragma unroll 2
    for (int s = 0; s < 12; s++) {
        uint32_t af[4][4];
#pragma unroll
        for (int mt = 0; mt < 4; mt++)
            ldm_x4(af[mt], aB + (a_row + mt * 16) * 400 + (uint32_t)s * 32 + a_cb);
#pragma unroll
        for (int np = 0; np < 4; np++) {
            uint32_t bf[4];
            ldm_x4(bf, bB + (b_row + np * 16) * 400 + (uint32_t)s * 32 + b_cb);
#pragma unroll
            for (int mt = 0; mt < 4; mt++) {
                mma_tf32(acc[mt][np * 2 + 0], af[mt], bf[0], bf[1]);
                mma_tf32(acc[mt][np * 2 + 1], af[mt], bf[2], bf[3]);
            }
        }
    }

    // epilogue: add bias, store half2 pairs
    const int rbase = m0 + wm * 64;
    const int cbase = n0 + wn * 64;
#pragma unroll
    for (int nt = 0; nt < 8; nt++) {
        int col = cbase + nt * 8 + (lid & 3) * 2;
        if (col + 1 >= WN) continue;
        float2 bb = *(const float2*)(b2 + col);
#pragma unroll
        for (int mt = 0; mt < 4; mt++) {
            int row = rbase + mt * 16 + (lid >> 2);
            __half* wp = g_w + (size_t)row * WN + col;
            if (row < E)
                *(__half2*)wp = __floats2half2_rn(acc[mt][nt][0] + bb.x, acc[mt][nt][1] + bb.y);
            if (row + 8 < E)
                *(__half2*)(wp + (size_t)8 * WN) = __floats2half2_rn(acc[mt][nt][2] + bb.x, acc[mt][nt][3] + bb.y);
        }
    }
}

// ---------------- per-edge tensor-product epilogue ----------------
__global__ __launch_bounds__(192) void tp_epilogue(const float* __restrict__ node_attr,
                                                   const int* __restrict__ edge_index,
                                                   const float* __restrict__ edge_sh,
                                                   int E) {
    const int e = blockIdx.x;
    if (e >= E) return;
    __shared__ float sx[IN_SIZE];
    __shared__ float sc0e[58];
    __shared__ float sc1o[204];
    __shared__ float sc1e[204];
    __shared__ float sc0o[58];
    __shared__ float ssh[4];
    __shared__ int s_src;

    const int t = threadIdx.x;
    if (t == 0) s_src = edge_index[e];
    if (t < 4) ssh[t] = edge_sh[(size_t)e * 4 + t];
    {
        const int dst = edge_index[E + e];
        const float* xr = node_attr + (size_t)dst * IN_SIZE;
        for (int i = t; i < IN_SIZE; i += 192) sx[i] = xr[i];
    }
    __syncthreads();

    const float sh0 = ssh[0], s1x = ssh[1], s1y = ssh[2], s1z = ssh[3];
    const float inv_s3 = 0.57735026918962576f;
    const float inv_s2 = 0.70710678118654752f;

    if (t < 58) {
        if (t < 48) sc0e[t] = sx[t] * sh0;
        else {
            int b = 48 + (t - 48) * 3;
            sc0e[t] = inv_s3 * (sx[b] * s1x + sx[b + 1] * s1y + sx[b + 2] * s1z);
        }
        if (t < 10) {
            int b = 78 + t * 3;
            sc0o[t] = inv_s3 * (sx[b] * s1x + sx[b + 1] * s1y + sx[b + 2] * s1z);
        } else {
            sc0o[t] = sx[108 + t - 10] * sh0;
        }
    }
    if (t < 68) {
        float v0, v1, v2;
        if (t < 48) {
            float xv = sx[t];
            v0 = xv * s1x; v1 = xv * s1y; v2 = xv * s1z;
        } else if (t < 58) {
            int b = 48 + (t - 48) * 3;
            v0 = sx[b] * sh0; v1 = sx[b + 1] * sh0; v2 = sx[b + 2] * sh0;
        } else {
            int b = 78 + (t - 58) * 3;
            float a0 = sx[b], a1 = sx[b + 1], a2 = sx[b + 2];
            v0 = (a1 * s1z - a2 * s1y) * inv_s2;
            v1 = (a2 * s1x - a0 * s1z) * inv_s2;
            v2 = (a0 * s1y - a1 * s1x) * inv_s2;
        }
        sc1o[t * 3 + 0] = v0; sc1o[t * 3 + 1] = v1; sc1o[t * 3 + 2] = v2;
        if (t < 10) {
            int b = 48 + t * 3;
            float a0 = sx[b], a1 = sx[b + 1], a2 = sx[b + 2];
            v0 = (a1 * s1z - a2 * s1y) * inv_s2;
            v1 = (a2 * s1x - a0 * s1z) * inv_s2;
            v2 = (a0 * s1y - a1 * s1x) * inv_s2;
        } else if (t < 20) {
            int b = 78 + (t - 10) * 3;
            v0 = sx[b] * sh0; v1 = sx[b + 1] * sh0; v2 = sx[b + 2] * sh0;
        } else {
            float xv = sx[108 + (t - 20)];
            v0 = xv * s1x; v1 = xv * s1y; v2 = xv * s1z;
        }
        sc1e[t * 3 + 0] = v0; sc1e[t * 3 + 1] = v1; sc1e[t * 3 + 2] = v2;
    }
    __syncthreads();

    const __half* wr = g_w + (size_t)e * WN;
    const float rs58 = 0.13130643285972254f;
    const float rs68 = 0.12126781251816648f;

    if (t < IN_SIZE) {
        float y = 0.0f;
        if (t < 48) {
#pragma unroll
            for (int i = 0; i < 58; i++)
                y += sc0e[i] * __half2float(__ldg(wr + OFF_0E + i * 48 + t));
            y *= rs58;
        } else if (t < 108) {
            const float* sc;
            int u, base;
            if (t < 78) { u = t - 48; base = OFF_1O; sc = sc1o; }
            else        { u = t - 78; base = OFF_1E; sc = sc1e; }
            int ov = u / 3;
            int c = u - ov * 3;
#pragma unroll
            for (int i = 0; i < 68; i++)
                y += sc[i * 3 + c] * __half2float(__ldg(wr + base + i * 10 + ov));
            y *= rs68;
        } else {
            int oo = t - 108;
#pragma unroll
            for (int i = 0; i < 58; i++)
                y += sc0o[i] * __half2float(__ldg(wr + OFF_0O + i * 48 + oo));
            y *= rs58;
        }
        atomicAdd(g_seg + (size_t)s_src * IN_SIZE + t, y);
    }
    if (t == IN_SIZE) atomicAdd(g_cnt + s_src, 1.0f);
}

// ---------------- finalize ----------------
__global__ void finalize_k(const float* __restrict__ node_attr,
                           float* __restrict__ out, int nn) {
    int i = blockIdx.x * blockDim.x + threadIdx.x;
    if (i < nn * IN_SIZE) {
        float c = g_cnt[i / IN_SIZE];
        out[i] = g_seg[i] / fmaxf(c, 1.0f) + node_attr[i];
    }
}

// ---------------- launch ----------------
extern "C" void kernel_launch(void* const* d_in, const int* in_sizes, int n_in,
                              void* d_out, int out_size) {
    const float* node_attr  = (const float*)d_in[0];
    const int*   edge_index = (const int*)d_in[1];
    const float* edge_attr  = (const float*)d_in[2];
    const float* edge_sh    = (const float*)d_in[3];
    const float* W1         = (const float*)d_in[4];
    const float* b1         = (const float*)d_in[5];
    const float* W2         = (const float*)d_in[6];
    const float* b2         = (const float*)d_in[7];
    float* out = (float*)d_out;

    const int E  = in_sizes[2] / HID;
    const int Nn = in_sizes[0] / IN_SIZE;

    zero_k<<<(Nn * IN_SIZE + 255) / 256, 256>>>(Nn);

    // h = relu(edge_attr @ W1 + b1) -> tf32-rounded fp32
    {
        dim3 grid((HID + 63) / 64, (E + 127) / 128);
        hgemm_k<<<grid, 256>>>(edge_attr, W1, b1, E);
    }

    // W2 -> transposed tf32
    convB_k<<<(HID * WN + 255) / 256, 256>>>(W2);

    // w = h @ W2 + b2 via tf32 HMMA (fp16 output)
    {
        const int dyn = 2 * OPER_B;   // 102400 bytes
        cudaFuncSetAttribute(wgemm_mma, cudaFuncAttributeMaxDynamicSharedMemorySize, dyn);
        dim3 grid((WN + 127) / 128, (E + 127) / 128);
        wgemm_mma<<<grid, 128, dyn>>>(b2, E);
    }

    tp_epilogue<<<E, 192>>>(node_attr, edge_index, edge_sh, E);

    finalize_k<<<(Nn * IN_SIZE + 255) / 256, 256>>>(node_attr, out, Nn);
}

// round 7
// speedup vs baseline: 2.5763x; 1.0052x over previous
#include <cuda_runtime.h>
#include <cuda_fp16.h>
#include <math.h>
#include <stdint.h>
#include <stddef.h>

// ---------------- problem constants ----------------
#define IN_SIZE 156          // 48 + 30 + 30 + 48
#define HID 96
#define WN 6928
#define MAX_E 50000
#define MAX_N 10000

// w segment offsets
#define OFF_0E 0
#define OFF_1O 2784
#define OFF_1E 3464
#define OFF_0O 4144

// ---------------- scratch (device globals) ----------------
__device__ float g_ha[(size_t)(MAX_E + 128) * HID];   // h, tf32-rounded fp32
__device__ float g_bt[(size_t)(WN + 128) * HID];      // W2^T, tf32-rounded fp32 [n][k]
__device__ __half g_w[(size_t)MAX_E * WN];            // w in fp16
__device__ float g_seg[(size_t)MAX_N * IN_SIZE];
__device__ float g_cnt[MAX_N];

// ---------------- PTX helpers (compute_103-safe) ----------------
__device__ __forceinline__ uint32_t smem_u32(const void* p) {
    uint32_t a;
    asm("{ .reg .u64 t; cvta.to.shared.u64 t, %1; cvt.u32.u64 %0, t; }" : "=r"(a) : "l"(p));
    return a;
}
__device__ __forceinline__ void cp16(uint32_t d, const void* s, bool v) {
    int sz = v ? 16 : 0;
    asm volatile("cp.async.cg.shared.global [%0], [%1], 16, %2;" :: "r"(d), "l"(s), "r"(sz) : "memory");
}
__device__ __forceinline__ void cp_commit() { asm volatile("cp.async.commit_group;" ::: "memory"); }
template<int N> __device__ __forceinline__ void cp_wait() { asm volatile("cp.async.wait_group %0;" :: "n"(N) : "memory"); }

__device__ __forceinline__ void ldm_x4(uint32_t* r, uint32_t addr) {
    asm volatile("ldmatrix.sync.aligned.m8n8.x4.shared.b16 {%0,%1,%2,%3}, [%4];"
                 : "=r"(r[0]), "=r"(r[1]), "=r"(r[2]), "=r"(r[3]) : "r"(addr));
}
__device__ __forceinline__ void mma_tf32(float* d, const uint32_t* a, uint32_t b0, uint32_t b1) {
    asm volatile("mma.sync.aligned.m16n8k8.row.col.f32.tf32.tf32.f32 "
                 "{%0,%1,%2,%3}, {%4,%5,%6,%7}, {%8,%9}, {%0,%1,%2,%3};"
                 : "+f"(d[0]), "+f"(d[1]), "+f"(d[2]), "+f"(d[3])
                 : "r"(a[0]), "r"(a[1]), "r"(a[2]), "r"(a[3]), "r"(b0), "r"(b1));
}
__device__ __forceinline__ float f2tf32(float f) {
    uint32_t r;
    asm("cvt.rna.tf32.f32 %0, %1;" : "=r"(r) : "f"(f));
    return __uint_as_float(r);
}

// ---------------- zero-init ----------------
__global__ void zero_k(int nn) {
    int i = blockIdx.x * blockDim.x + threadIdx.x;
    int ns = nn * IN_SIZE;
    if (i < ns) g_seg[i] = 0.0f;
    if (i < nn) g_cnt[i] = 0.0f;
}

// ---------------- h GEMM (fp32 SIMT): g_ha = tf32(relu(edge_attr@W1 + b1)) ----------------
__global__ __launch_bounds__(256) void hgemm_k(const float* __restrict__ A,
                                               const float* __restrict__ B,
                                               const float* __restrict__ bias,
                                               int M) {
    __shared__ float sA[48 * 132];
    __shared__ float sB[48 * 64];

    const int n0 = blockIdx.x * 64;
    const int m0 = blockIdx.y * 128;
    const int tid = threadIdx.x;
    const int tmi = tid >> 4;
    const int tni = tid & 15;

    float acc[8][4];
#pragma unroll
    for (int mm = 0; mm < 8; mm++)
#pragma unroll
        for (int nn = 0; nn < 4; nn++) acc[mm][nn] = 0.0f;

#pragma unroll
    for (int p = 0; p < 2; p++) {
        const int kb = p * 48;
#pragma unroll
        for (int it = 0; it < 6; it++) {
            int idx = tid + it * 256;
            int e = idx / 12;
            int k4 = idx % 12;
            float4 v = make_float4(0.f, 0.f, 0.f, 0.f);
            if (m0 + e < M)
                v = *(const float4*)(A + (size_t)(m0 + e) * HID + kb + k4 * 4);
            sA[(k4 * 4 + 0) * 132 + e] = v.x;
            sA[(k4 * 4 + 1) * 132 + e] = v.y;
            sA[(k4 * 4 + 2) * 132 + e] = v.z;
            sA[(k4 * 4 + 3) * 132 + e] = v.w;
        }
#pragma unroll
        for (int it = 0; it < 3; it++) {
            int idx = tid + it * 256;
            int k = idx / 16;
            int j4 = idx % 16;
            int j = n0 + j4 * 4;
            float4 v = make_float4(0.f, 0.f, 0.f, 0.f);
            if (j < HID)
                v = *(const float4*)(B + (size_t)(kb + k) * HID + j);
            *(float4*)(sB + k * 64 + j4 * 4) = v;
        }
        __syncthreads();

#pragma unroll 8
        for (int k = 0; k < 48; k++) {
            float4 a0 = *(float4*)(sA + k * 132 + tmi * 8);
            float4 a1 = *(float4*)(sA + k * 132 + tmi * 8 + 4);
            float4 b = *(float4*)(sB + k * 64 + tni * 4);
            float av[8] = {a0.x, a0.y, a0.z, a0.w, a1.x, a1.y, a1.z, a1.w};
            float bv[4] = {b.x, b.y, b.z, b.w};
#pragma unroll
            for (int mm = 0; mm < 8; mm++)
#pragma unroll
                for (int nn = 0; nn < 4; nn++)
                    acc[mm][nn] += av[mm] * bv[nn];
        }
        __syncthreads();
    }

    const int n = n0 + tni * 4;
#pragma unroll
    for (int mm = 0; mm < 8; mm++) {
        int e = m0 + tmi * 8 + mm;
        if (e >= M) continue;
        size_t rb = (size_t)e * HID;
#pragma unroll
        for (int nn = 0; nn < 4; nn++) {
            int nc = n + nn;
            if (nc >= HID) continue;
            float v = fmaxf(acc[mm][nn] + bias[nc], 0.0f);
            g_ha[rb + nc] = f2tf32(v);
        }
    }
}

// ---------------- B conversion: W2[96][6928] fp32 -> g_bt[6928][96] tf32 ----------------
__global__ void convB_k(const float* __restrict__ W2) {
    int i = blockIdx.x * blockDim.x + threadIdx.x;
    if (i >= HID * WN) return;
    int k = i / WN;
    int n = i - k * WN;
    g_bt[(size_t)n * HID + k] = f2tf32(W2[i]);
}

// ---------------- w GEMM via mma.sync tf32 (K=96, no split) ----------------
// 128x128 CTA tile, 4 warps (2M x 2N), warp tile 64x64. Single-stage full-K smem.
// Row stride 100 floats (400B) -> conflict-free ldmatrix phases. 2 CTAs/SM.
#define ASTR 100                 // smem row stride in floats
#define OPER_B (128 * ASTR * 4)  // bytes per operand (51200)
__global__ __launch_bounds__(128, 2) void wgemm_mma(const float* __restrict__ b2, int E) {
    extern __shared__ __align__(16) float smem[];

    const int tid = threadIdx.x;
    const int wid = tid >> 5;
    const int lid = tid & 31;
    const int wm = wid >> 1;     // 0..1 -> rows wm*64
    const int wn = wid & 1;      // 0..1 -> cols wn*64
    const int n0 = blockIdx.x * 128;
    const int m0 = blockIdx.y * 128;

    const uint32_t aB = smem_u32(smem);
    const uint32_t bB = aB + OPER_B;

    // load full K=96 for A(128 rows) and B(128 rows): 6144 x 16B chunks
#pragma unroll
    for (int i = 0; i < 48; i++) {
        int idx = tid + i * 128;          // 0..6143
        if (idx < 3072) {
            int row = idx / 24, ch = idx % 24;
            bool v = (m0 + row) < E;
            int r = v ? (m0 + row) : 0;
            cp16(aB + (uint32_t)(row * 400 + ch * 16), g_ha + (size_t)r * HID + ch * 4, v);
        } else {
            int l = idx - 3072;
            int row = l / 24, ch = l % 24;
            bool v = (n0 + row) < WN;
            int r = v ? (n0 + row) : 0;
            cp16(bB + (uint32_t)(row * 400 + ch * 16), g_bt + (size_t)r * HID + ch * 4, v);
        }
    }
    cp_commit();

    float acc[4][8][4];
#pragma unroll
    for (int mt = 0; mt < 4; mt++)
#pragma unroll
        for (int nt = 0; nt < 8; nt++)
#pragma unroll
            for (int q = 0; q < 4; q++) acc[mt][nt][q] = 0.0f;

    // per-lane ldmatrix addressing (tf32: 8x8 b16 tile == 8x4 tf32 tile)
    const uint32_t a_row = (uint32_t)(wm * 64 + (lid & 15));
    const uint32_t a_cb  = (uint32_t)((lid >> 4) * 16);            // byte col offset
    const uint32_t b_row = (uint32_t)(wn * 64 + (lid & 7) + ((lid >> 4) << 3));
    const uint32_t b_cb  = (uint32_t)(((lid >> 3) & 1) * 16);

    cp_wait<0>();
    __syncthreads();

#pragma unroll 2
    for (int s = 0; s < 12; s++) {
        uint32_t af[4][4];
#pragma unroll
        for (int mt = 0; mt < 4; mt++)
            ldm_x4(af[mt], aB + (a_row + mt * 16) * 400 + (uint32_t)s * 32 + a_cb);
#pragma unroll
        for (int np = 0; np < 4; np++) {
            uint32_t bf[4];
            ldm_x4(bf, bB + (b_row + np * 16) * 400 + (uint32_t)s * 32 + b_cb);
#pragma unroll
            for (int mt = 0; mt < 4; mt++) {
                mma_tf32(acc[mt][np * 2 + 0], af[mt], bf[0], bf[1]);
                mma_tf32(acc[mt][np * 2 + 1], af[mt], bf[2], bf[3]);
            }
        }
    }

    // epilogue: add bias, store half2 pairs
    const int rbase = m0 + wm * 64;
    const int cbase = n0 + wn * 64;
#pragma unroll
    for (int nt = 0; nt < 8; nt++) {
        int col = cbase + nt * 8 + (lid & 3) * 2;
        if (col + 1 >= WN) continue;
        float2 bb = *(const float2*)(b2 + col);
#pragma unroll
        for (int mt = 0; mt < 4; mt++) {
            int row = rbase + mt * 16 + (lid >> 2);
            __half* wp = g_w + (size_t)row * WN + col;
            if (row < E)
                *(__half2*)wp = __floats2half2_rn(acc[mt][nt][0] + bb.x, acc[mt][nt][1] + bb.y);
            if (row + 8 < E)
                *(__half2*)(wp + (size_t)8 * WN) = __floats2half2_rn(acc[mt][nt][2] + bb.x, acc[mt][nt][3] + bb.y);
        }
    }
}

// ---------------- per-edge tensor-product epilogue ----------------
__global__ __launch_bounds__(192) void tp_epilogue(const float* __restrict__ node_attr,
                                                   const int* __restrict__ edge_index,
                                                   const float* __restrict__ edge_sh,
                                                   int E) {
    const int e = blockIdx.x;
    if (e >= E) return;
    __shared__ float sx[IN_SIZE];
    __shared__ float sc0e[58];
    __shared__ float sc1o[204];
    __shared__ float sc1e[204];
    __shared__ float sc0o[58];
    __shared__ float ssh[4];
    __shared__ int s_src;

    const int t = threadIdx.x;
    if (t == 0) s_src = edge_index[e];
    if (t < 4) ssh[t] = edge_sh[(size_t)e * 4 + t];
    {
        const int dst = edge_index[E + e];
        const float* xr = node_attr + (size_t)dst * IN_SIZE;
        for (int i = t; i < IN_SIZE; i += 192) sx[i] = xr[i];
    }
    __syncthreads();

    const float sh0 = ssh[0], s1x = ssh[1], s1y = ssh[2], s1z = ssh[3];
    const float inv_s3 = 0.57735026918962576f;
    const float inv_s2 = 0.70710678118654752f;

    if (t < 58) {
        if (t < 48) sc0e[t] = sx[t] * sh0;
        else {
            int b = 48 + (t - 48) * 3;
            sc0e[t] = inv_s3 * (sx[b] * s1x + sx[b + 1] * s1y + sx[b + 2] * s1z);
        }
        if (t < 10) {
            int b = 78 + t * 3;
            sc0o[t] = inv_s3 * (sx[b] * s1x + sx[b + 1] * s1y + sx[b + 2] * s1z);
        } else {
            sc0o[t] = sx[108 + t - 10] * sh0;
        }
    }
    if (t < 68) {
        float v0, v1, v2;
        if (t < 48) {
            float xv = sx[t];
            v0 = xv * s1x; v1 = xv * s1y; v2 = xv * s1z;
        } else if (t < 58) {
            int b = 48 + (t - 48) * 3;
            v0 = sx[b] * sh0; v1 = sx[b + 1] * sh0; v2 = sx[b + 2] * sh0;
        } else {
            int b = 78 + (t - 58) * 3;
            float a0 = sx[b], a1 = sx[b + 1], a2 = sx[b + 2];
            v0 = (a1 * s1z - a2 * s1y) * inv_s2;
            v1 = (a2 * s1x - a0 * s1z) * inv_s2;
            v2 = (a0 * s1y - a1 * s1x) * inv_s2;
        }
        sc1o[t * 3 + 0] = v0; sc1o[t * 3 + 1] = v1; sc1o[t * 3 + 2] = v2;
        if (t < 10) {
            int b = 48 + t * 3;
            float a0 = sx[b], a1 = sx[b + 1], a2 = sx[b + 2];
            v0 = (a1 * s1z - a2 * s1y) * inv_s2;
            v1 = (a2 * s1x - a0 * s1z) * inv_s2;
            v2 = (a0 * s1y - a1 * s1x) * inv_s2;
        } else if (t < 20) {
            int b = 78 + (t - 10) * 3;
            v0 = sx[b] * sh0; v1 = sx[b + 1] * sh0; v2 = sx[b + 2] * sh0;
        } else {
            float xv = sx[108 + (t - 20)];
            v0 = xv * s1x; v1 = xv * s1y; v2 = xv * s1z;
        }
        sc1e[t * 3 + 0] = v0; sc1e[t * 3 + 1] = v1; sc1e[t * 3 + 2] = v2;
    }
    __syncthreads();

    const __half* wr = g_w + (size_t)e * WN;
    const float rs58 = 0.13130643285972254f;
    const float rs68 = 0.12126781251816648f;

    if (t < IN_SIZE) {
        float y = 0.0f;
        if (t < 48) {
#pragma unroll
            for (int i = 0; i < 58; i++)
                y += sc0e[i] * __half2float(__ldg(wr + OFF_0E + i * 48 + t));
            y *= rs58;
        } else if (t < 108) {
            const float* sc;
            int u, base;
            if (t < 78) { u = t - 48; base = OFF_1O; sc = sc1o; }
            else        { u = t - 78; base = OFF_1E; sc = sc1e; }
            int ov = u / 3;
            int c = u - ov * 3;
#pragma unroll
            for (int i = 0; i < 68; i++)
                y += sc[i * 3 + c] * __half2float(__ldg(wr + base + i * 10 + ov));
            y *= rs68;
        } else {
            int oo = t - 108;
#pragma unroll
            for (int i = 0; i < 58; i++)
                y += sc0o[i] * __half2float(__ldg(wr + OFF_0O + i * 48 + oo));
            y *= rs58;
        }
        atomicAdd(g_seg + (size_t)s_src * IN_SIZE + t, y);
    }
    if (t == IN_SIZE) atomicAdd(g_cnt + s_src, 1.0f);
}

// ---------------- finalize ----------------
__global__ void finalize_k(const float* __restrict__ node_attr,
                           float* __restrict__ out, int nn) {
    int i = blockIdx.x * blockDim.x + threadIdx.x;
    if (i < nn * IN_SIZE) {
        float c = g_cnt[i / IN_SIZE];
        out[i] = g_seg[i] / fmaxf(c, 1.0f) + node_attr[i];
    }
}

// ---------------- launch ----------------
extern "C" void kernel_launch(void* const* d_in, const int* in_sizes, int n_in,
                              void* d_out, int out_size) {
    const float* node_attr  = (const float*)d_in[0];
    const int*   edge_index = (const int*)d_in[1];
    const float* edge_attr  = (const float*)d_in[2];
    const float* edge_sh    = (const float*)d_in[3];
    const float* W1         = (const float*)d_in[4];
    const float* b1         = (const float*)d_in[5];
    const float* W2         = (const float*)d_in[6];
    const float* b2         = (const float*)d_in[7];
    float* out = (float*)d_out;

    const int E  = in_sizes[2] / HID;
    const int Nn = in_sizes[0] / IN_SIZE;

    zero_k<<<(Nn * IN_SIZE + 255) / 256, 256>>>(Nn);

    // h = relu(edge_attr @ W1 + b1) -> tf32-rounded fp32
    {
        dim3 grid((HID + 63) / 64, (E + 127) / 128);
        hgemm_k<<<grid, 256>>>(edge_attr, W1, b1, E);
    }

    // W2 -> transposed tf32
    convB_k<<<(HID * WN + 255) / 256, 256>>>(W2);

    // w = h @ W2 + b2 via tf32 HMMA (fp16 output)
    {
        const int dyn = 2 * OPER_B;   // 102400 bytes
        cudaFuncSetAttribute(wgemm_mma, cudaFuncAttributeMaxDynamicSharedMemorySize, dyn);
        dim3 grid((WN + 127) / 128, (E + 127) / 128);
        wgemm_mma<<<grid, 128, dyn>>>(b2, E);
    }

    tp_epilogue<<<E, 192>>>(node_attr, edge_index, edge_sh, E);

    finalize_k<<<(Nn * IN_SIZE + 255) / 256, 256>>>(node_attr, out, Nn);
}

// round 8
// speedup vs baseline: 2.5816x; 1.0020x over previous
#include <cuda_runtime.h>
#include <cuda_fp16.h>
#include <math.h>
#include <stdint.h>
#include <stddef.h>

// ---------------- problem constants ----------------
#define IN_SIZE 156          // 48 + 30 + 30 + 48
#define HID 96
#define WN 6928
#define MAX_E 50000
#define MAX_N 10000

// w segment offsets
#define OFF_0E 0
#define OFF_1O 2784
#define OFF_1E 3464
#define OFF_0O 4144

// ---------------- scratch (device globals) ----------------
__device__ float g_ha[(size_t)(MAX_E + 128) * HID];   // h, tf32-rounded fp32
__device__ float g_bt[(size_t)(WN + 128) * HID];      // W2^T, tf32-rounded fp32 [n][k]
__device__ __half g_w[(size_t)MAX_E * WN];            // w in fp16
__device__ float g_seg[(size_t)MAX_N * IN_SIZE];
__device__ float g_cnt[MAX_N];

// ---------------- PTX helpers (compute_103-safe) ----------------
__device__ __forceinline__ uint32_t smem_u32(const void* p) {
    uint32_t a;
    asm("{ .reg .u64 t; cvta.to.shared.u64 t, %1; cvt.u32.u64 %0, t; }" : "=r"(a) : "l"(p));
    return a;
}
__device__ __forceinline__ void cp16(uint32_t d, const void* s, bool v) {
    int sz = v ? 16 : 0;
    asm volatile("cp.async.cg.shared.global [%0], [%1], 16, %2;" :: "r"(d), "l"(s), "r"(sz) : "memory");
}
__device__ __forceinline__ void cp_commit() { asm volatile("cp.async.commit_group;" ::: "memory"); }
template<int N> __device__ __forceinline__ void cp_wait() { asm volatile("cp.async.wait_group %0;" :: "n"(N) : "memory"); }

__device__ __forceinline__ void ldm_x4(uint32_t* r, uint32_t addr) {
    asm volatile("ldmatrix.sync.aligned.m8n8.x4.shared.b16 {%0,%1,%2,%3}, [%4];"
                 : "=r"(r[0]), "=r"(r[1]), "=r"(r[2]), "=r"(r[3]) : "r"(addr));
}
__device__ __forceinline__ void mma_tf32(float* d, const uint32_t* a, uint32_t b0, uint32_t b1) {
    asm volatile("mma.sync.aligned.m16n8k8.row.col.f32.tf32.tf32.f32 "
                 "{%0,%1,%2,%3}, {%4,%5,%6,%7}, {%8,%9}, {%0,%1,%2,%3};"
                 : "+f"(d[0]), "+f"(d[1]), "+f"(d[2]), "+f"(d[3])
                 : "r"(a[0]), "r"(a[1]), "r"(a[2]), "r"(a[3]), "r"(b0), "r"(b1));
}
__device__ __forceinline__ float f2tf32(float f) {
    uint32_t r;
    asm("cvt.rna.tf32.f32 %0, %1;" : "=r"(r) : "f"(f));
    return __uint_as_float(r);
}

// ---------------- zero-init ----------------
__global__ void zero_k(int nn) {
    int i = blockIdx.x * blockDim.x + threadIdx.x;
    int ns = nn * IN_SIZE;
    if (i < ns) g_seg[i] = 0.0f;
    if (i < nn) g_cnt[i] = 0.0f;
}

// ---------------- h GEMM (fp32 SIMT): g_ha = tf32(relu(edge_attr@W1 + b1)) ----------------
__global__ __launch_bounds__(256) void hgemm_k(const float* __restrict__ A,
                                               const float* __restrict__ B,
                                               const float* __restrict__ bias,
                                               int M) {
    __shared__ float sA[48 * 132];
    __shared__ float sB[48 * 64];

    const int n0 = blockIdx.x * 64;
    const int m0 = blockIdx.y * 128;
    const int tid = threadIdx.x;
    const int tmi = tid >> 4;
    const int tni = tid & 15;

    float acc[8][4];
#pragma unroll
    for (int mm = 0; mm < 8; mm++)
#pragma unroll
        for (int nn = 0; nn < 4; nn++) acc[mm][nn] = 0.0f;

#pragma unroll
    for (int p = 0; p < 2; p++) {
        const int kb = p * 48;
#pragma unroll
        for (int it = 0; it < 6; it++) {
            int idx = tid + it * 256;
            int e = idx / 12;
            int k4 = idx % 12;
            float4 v = make_float4(0.f, 0.f, 0.f, 0.f);
            if (m0 + e < M)
                v = *(const float4*)(A + (size_t)(m0 + e) * HID + kb + k4 * 4);
            sA[(k4 * 4 + 0) * 132 + e] = v.x;
            sA[(k4 * 4 + 1) * 132 + e] = v.y;
            sA[(k4 * 4 + 2) * 132 + e] = v.z;
            sA[(k4 * 4 + 3) * 132 + e] = v.w;
        }
#pragma unroll
        for (int it = 0; it < 3; it++) {
            int idx = tid + it * 256;
            int k = idx / 16;
            int j4 = idx % 16;
            int j = n0 + j4 * 4;
            float4 v = make_float4(0.f, 0.f, 0.f, 0.f);
            if (j < HID)
                v = *(const float4*)(B + (size_t)(kb + k) * HID + j);
            *(float4*)(sB + k * 64 + j4 * 4) = v;
        }
        __syncthreads();

#pragma unroll 8
        for (int k = 0; k < 48; k++) {
            float4 a0 = *(float4*)(sA + k * 132 + tmi * 8);
            float4 a1 = *(float4*)(sA + k * 132 + tmi * 8 + 4);
            float4 b = *(float4*)(sB + k * 64 + tni * 4);
            float av[8] = {a0.x, a0.y, a0.z, a0.w, a1.x, a1.y, a1.z, a1.w};
            float bv[4] = {b.x, b.y, b.z, b.w};
#pragma unroll
            for (int mm = 0; mm < 8; mm++)
#pragma unroll
                for (int nn = 0; nn < 4; nn++)
                    acc[mm][nn] += av[mm] * bv[nn];
        }
        __syncthreads();
    }

    const int n = n0 + tni * 4;
#pragma unroll
    for (int mm = 0; mm < 8; mm++) {
        int e = m0 + tmi * 8 + mm;
        if (e >= M) continue;
        size_t rb = (size_t)e * HID;
#pragma unroll
        for (int nn = 0; nn < 4; nn++) {
            int nc = n + nn;
            if (nc >= HID) continue;
            float v = fmaxf(acc[mm][nn] + bias[nc], 0.0f);
            g_ha[rb + nc] = f2tf32(v);
        }
    }
}

// ---------------- B conversion: W2[96][6928] fp32 -> g_bt[6928][96] tf32 ----------------
__global__ void convB_k(const float* __restrict__ W2) {
    int i = blockIdx.x * blockDim.x + threadIdx.x;
    if (i >= HID * WN) return;
    int k = i / WN;
    int n = i - k * WN;
    g_bt[(size_t)n * HID + k] = f2tf32(W2[i]);
}

// ---------------- w GEMM via mma.sync tf32 (K=96, no split) ----------------
// 128x128 CTA tile, 4 warps (2M x 2N), warp tile 64x64. Single-stage full-K smem.
// Row stride 100 floats (400B) -> conflict-free ldmatrix phases. 2 CTAs/SM.
#define ASTR 100                 // smem row stride in floats
#define OPER_B (128 * ASTR * 4)  // bytes per operand (51200)
__global__ __launch_bounds__(128, 2) void wgemm_mma(const float* __restrict__ b2, int E) {
    extern __shared__ __align__(16) float smem[];

    const int tid = threadIdx.x;
    const int wid = tid >> 5;
    const int lid = tid & 31;
    const int wm = wid >> 1;     // 0..1 -> rows wm*64
    const int wn = wid & 1;      // 0..1 -> cols wn*64
    const int n0 = blockIdx.x * 128;
    const int m0 = blockIdx.y * 128;

    const uint32_t aB = smem_u32(smem);
    const uint32_t bB = aB + OPER_B;

    // load full K=96 for A(128 rows) and B(128 rows): 6144 x 16B chunks
#pragma unroll
    for (int i = 0; i < 48; i++) {
        int idx = tid + i * 128;          // 0..6143
        if (idx < 3072) {
            int row = idx / 24, ch = idx % 24;
            bool v = (m0 + row) < E;
            int r = v ? (m0 + row) : 0;
            cp16(aB + (uint32_t)(row * 400 + ch * 16), g_ha + (size_t)r * HID + ch * 4, v);
        } else {
            int l = idx - 3072;
            int row = l / 24, ch = l % 24;
            bool v = (n0 + row) < WN;
            int r = v ? (n0 + row) : 0;
            cp16(bB + (uint32_t)(row * 400 + ch * 16), g_bt + (size_t)r * HID + ch * 4, v);
        }
    }
    cp_commit();

    float acc[4][8][4];
#pragma unroll
    for (int mt = 0; mt < 4; mt++)
#pragma unroll
        for (int nt = 0; nt < 8; nt++)
#pragma unroll
            for (int q = 0; q < 4; q++) acc[mt][nt][q] = 0.0f;

    // per-lane ldmatrix addressing (tf32: 8x8 b16 tile == 8x4 tf32 tile)
    const uint32_t a_row = (uint32_t)(wm * 64 + (lid & 15));
    const uint32_t a_cb  = (uint32_t)((lid >> 4) * 16);            // byte col offset
    const uint32_t b_row = (uint32_t)(wn * 64 + (lid & 7) + ((lid >> 4) << 3));
    const uint32_t b_cb  = (uint32_t)(((lid >> 3) & 1) * 16);

    cp_wait<0>();
    __syncthreads();

#pragma unroll 2
    for (int s = 0; s < 12; s++) {
        uint32_t af[4][4];
#pragma unroll
        for (int mt = 0; mt < 4; mt++)
            ldm_x4(af[mt], aB + (a_row + mt * 16) * 400 + (uint32_t)s * 32 + a_cb);
#pragma unroll
        for (int np = 0; np < 4; np++) {
            uint32_t bf[4];
            ldm_x4(bf, bB + (b_row + np * 16) * 400 + (uint32_t)s * 32 + b_cb);
#pragma unroll
            for (int mt = 0; mt < 4; mt++) {
                mma_tf32(acc[mt][np * 2 + 0], af[mt], bf[0], bf[1]);
                mma_tf32(acc[mt][np * 2 + 1], af[mt], bf[2], bf[3]);
            }
        }
    }

    // epilogue: add bias, store half2 pairs
    const int rbase = m0 + wm * 64;
    const int cbase = n0 + wn * 64;
#pragma unroll
    for (int nt = 0; nt < 8; nt++) {
        int col = cbase + nt * 8 + (lid & 3) * 2;
        if (col + 1 >= WN) continue;
        float2 bb = *(const float2*)(b2 + col);
#pragma unroll
        for (int mt = 0; mt < 4; mt++) {
            int row = rbase + mt * 16 + (lid >> 2);
            __half* wp = g_w + (size_t)row * WN + col;
            if (row < E)
                *(__half2*)wp = __floats2half2_rn(acc[mt][nt][0] + bb.x, acc[mt][nt][1] + bb.y);
            if (row + 8 < E)
                *(__half2*)(wp + (size_t)8 * WN) = __floats2half2_rn(acc[mt][nt][2] + bb.x, acc[mt][nt][3] + bb.y);
        }
    }
}

// ---------------- per-edge tensor-product epilogue ----------------
__global__ __launch_bounds__(192) void tp_epilogue(const float* __restrict__ node_attr,
                                                   const int* __restrict__ edge_index,
                                                   const float* __restrict__ edge_sh,
                                                   int E) {
    const int e = blockIdx.x;
    if (e >= E) return;
    __shared__ float sx[IN_SIZE];
    __shared__ float sc0e[58];
    __shared__ float sc1o[204];
    __shared__ float sc1e[204];
    __shared__ float sc0o[58];
    __shared__ float ssh[4];
    __shared__ int s_src;

    const int t = threadIdx.x;
    if (t == 0) s_src = edge_index[e];
    if (t < 4) ssh[t] = edge_sh[(size_t)e * 4 + t];
    {
        const int dst = edge_index[E + e];
        const float* xr = node_attr + (size_t)dst * IN_SIZE;
        for (int i = t; i < IN_SIZE; i += 192) sx[i] = xr[i];
    }
    __syncthreads();

    const float sh0 = ssh[0], s1x = ssh[1], s1y = ssh[2], s1z = ssh[3];
    const float inv_s3 = 0.57735026918962576f;
    const float inv_s2 = 0.70710678118654752f;

    if (t < 58) {
        if (t < 48) sc0e[t] = sx[t] * sh0;
        else {
            int b = 48 + (t - 48) * 3;
            sc0e[t] = inv_s3 * (sx[b] * s1x + sx[b + 1] * s1y + sx[b + 2] * s1z);
        }
        if (t < 10) {
            int b = 78 + t * 3;
            sc0o[t] = inv_s3 * (sx[b] * s1x + sx[b + 1] * s1y + sx[b + 2] * s1z);
        } else {
            sc0o[t] = sx[108 + t - 10] * sh0;
        }
    }
    if (t < 68) {
        float v0, v1, v2;
        if (t < 48) {
            float xv = sx[t];
            v0 = xv * s1x; v1 = xv * s1y; v2 = xv * s1z;
        } else if (t < 58) {
            int b = 48 + (t - 48) * 3;
            v0 = sx[b] * sh0; v1 = sx[b + 1] * sh0; v2 = sx[b + 2] * sh0;
        } else {
            int b = 78 + (t - 58) * 3;
            float a0 = sx[b], a1 = sx[b + 1], a2 = sx[b + 2];
            v0 = (a1 * s1z - a2 * s1y) * inv_s2;
            v1 = (a2 * s1x - a0 * s1z) * inv_s2;
            v2 = (a0 * s1y - a1 * s1x) * inv_s2;
        }
        sc1o[t * 3 + 0] = v0; sc1o[t * 3 + 1] = v1; sc1o[t * 3 + 2] = v2;
        if (t < 10) {
            int b = 48 + t * 3;
            float a0 = sx[b], a1 = sx[b + 1], a2 = sx[b + 2];
            v0 = (a1 * s1z - a2 * s1y) * inv_s2;
            v1 = (a2 * s1x - a0 * s1z) * inv_s2;
            v2 = (a0 * s1y - a1 * s1x) * inv_s2;
        } else if (t < 20) {
            int b = 78 + (t - 10) * 3;
            v0 = sx[b] * sh0; v1 = sx[b + 1] * sh0; v2 = sx[b + 2] * sh0;
        } else {
            float xv = sx[108 + (t - 20)];
            v0 = xv * s1x; v1 = xv * s1y; v2 = xv * s1z;
        }
        sc1e[t * 3 + 0] = v0; sc1e[t * 3 + 1] = v1; sc1e[t * 3 + 2] = v2;
    }
    __syncthreads();

    const __half* wr = g_w + (size_t)e * WN;
    const float rs58 = 0.13130643285972254f;
    const float rs68 = 0.12126781251816648f;

    if (t < IN_SIZE) {
        float y = 0.0f;
        if (t < 48) {
#pragma unroll
            for (int i = 0; i < 58; i++)
                y += sc0e[i] * __half2float(__ldg(wr + OFF_0E + i * 48 + t));
            y *= rs58;
        } else if (t < 108) {
            const float* sc;
            int u, base;
            if (t < 78) { u = t - 48; base = OFF_1O; sc = sc1o; }
            else        { u = t - 78; base = OFF_1E; sc = sc1e; }
            int ov = u / 3;
            int c = u - ov * 3;
#pragma unroll
            for (int i = 0; i < 68; i++)
                y += sc[i * 3 + c] * __half2float(__ldg(wr + base + i * 10 + ov));
            y *= rs68;
        } else {
            int oo = t - 108;
#pragma unroll
            for (int i = 0; i < 58; i++)
                y += sc0o[i] * __half2float(__ldg(wr + OFF_0O + i * 48 + oo));
            y *= rs58;
        }
        atomicAdd(g_seg + (size_t)s_src * IN_SIZE + t, y);
    }
    if (t == IN_SIZE) atomicAdd(g_cnt + s_src, 1.0f);
}

// ---------------- finalize ----------------
__global__ void finalize_k(const float* __restrict__ node_attr,
                           float* __restrict__ out, int nn) {
    int i = blockIdx.x * blockDim.x + threadIdx.x;
    if (i < nn * IN_SIZE) {
        float c = g_cnt[i / IN_SIZE];
        out[i] = g_seg[i] / fmaxf(c, 1.0f) + node_attr[i];
    }
}

// ---------------- launch ----------------
extern "C" void kernel_launch(void* const* d_in, const int* in_sizes, int n_in,
                              void* d_out, int out_size) {
    const float* node_attr  = (const float*)d_in[0];
    const int*   edge_index = (const int*)d_in[1];
    const float* edge_attr  = (const float*)d_in[2];
    const float* edge_sh    = (const float*)d_in[3];
    const float* W1         = (const float*)d_in[4];
    const float* b1         = (const float*)d_in[5];
    const float* W2         = (const float*)d_in[6];
    const float* b2         = (const float*)d_in[7];
    float* out = (float*)d_out;

    const int E  = in_sizes[2] / HID;
    const int Nn = in_sizes[0] / IN_SIZE;

    zero_k<<<(Nn * IN_SIZE + 255) / 256, 256>>>(Nn);

    // h = relu(edge_attr @ W1 + b1) -> tf32-rounded fp32
    {
        dim3 grid((HID + 63) / 64, (E + 127) / 128);
        hgemm_k<<<grid, 256>>>(edge_attr, W1, b1, E);
    }

    // W2 -> transposed tf32
    convB_k<<<(HID * WN + 255) / 256, 256>>>(W2);

    // w = h @ W2 + b2 via tf32 HMMA (fp16 output)
    {
        const int dyn = 2 * OPER_B;   // 102400 bytes
        cudaFuncSetAttribute(wgemm_mma, cudaFuncAttributeMaxDynamicSharedMemorySize, dyn);
        dim3 grid((WN + 127) / 128, (E + 127) / 128);
        wgemm_mma<<<grid, 128, dyn>>>(b2, E);
    }

    tp_epilogue<<<E, 192>>>(node_attr, edge_index, edge_sh, E);

    finalize_k<<<(Nn * IN_SIZE + 255) / 256, 256>>>(node_attr, out, Nn);
}